// round 14
// baseline (speedup 1.0000x reference)
#include <cuda_runtime.h>
#include <cuda_fp16.h>
#include <mma.h>
#include <math.h>

using namespace nvcuda;

#define NN 100000
#define EE 1600000
#define GG 256
#define NCLS 10
#define F6 768
#define SCAP 192
#define NEG 0.2f
#define NB 98  // cdiv(NN, 1024)
#define NNL ((long long)NN)

#define LDH 136  // half-element leading dim for A/W smem tiles
#define WS_BYTES (128 * LDH * 2)
#define AS_BYTES (128 * LDH * 2)
#define EST_BYTES (16 * 256 * 4)  // per-warp 16x16 fp32 staging, 16 warps
#define GEMM_SMEM_BYTES (WS_BYTES + AS_BYTES + EST_BYTES)

static inline int cdiv(int a, int b) { return (a + b - 1) / b; }

// ---------------- device scratch (no allocations allowed) ----------------
__device__ int    g_cntR[NN];
__device__ int    g_cntC[NN];
__device__ int    g_startR[NN + 1];
__device__ int    g_startC[NN + 1];
__device__ int    g_curR[NN];
__device__ int    g_curC[NN];
__device__ int    g_inclR[NN];
__device__ int    g_inclC[NN];
__device__ int    g_bsumR[NB];
__device__ int    g_bsumC[NB];
__device__ int    g_col[EE];        // CSR (by source): dest of each slot
__device__ int    g_crow[EE];       // CSC (by dest): source of each slot
__device__ int    g_cpidx[EE];      // CSC slot -> CSR slot
__device__ float  g_p[3 * EE];      // sparsemax weights, CSR order, per block
__device__ __align__(16) float2 g_ecc[3ll * EE];  // compacted live edges (u, ec)
__device__ int    g_lcnt[3 * NN];   // live-edge count per (block, dest)
__device__ float  g_s1[3 * NN];
__device__ float  g_s2[3 * NN];
__device__ float  g_dinv[3 * NN];
__device__ __align__(16) __half g_h16A[3ll * NN * 128];  // conv1 gemm out / conv2 gather out
__device__ __align__(16) __half g_h16B[3ll * NN * 128];  // conv1 gather out (gemm2 in)
__device__ __align__(16) __half g_h16C[3ll * NN * 128];  // conv2 gemm out
__device__ float  g_feats[GG * F6];
__device__ float  g_mlp1[GG * 256];
__device__ float  g_mlp2[GG * 128];
__device__ int    g_cntg[GG];

// ---------------- CSR + CSC build ----------------
__global__ void hist_e(const int* __restrict__ row, const int* __restrict__ col) {
    int e = blockIdx.x * blockDim.x + threadIdx.x;
    if (e >= EE) return;
    atomicAdd(&g_cntR[row[e]], 1);
    atomicAdd(&g_cntC[col[e]], 1);
}

__device__ __forceinline__ void block_incl_scan(int* sh, int tid) {
#pragma unroll
    for (int off = 1; off < 1024; off <<= 1) {
        int t = (tid >= off) ? sh[tid - off] : 0;
        __syncthreads();
        sh[tid] += t;
        __syncthreads();
    }
}

__global__ void scan_local(const int* __restrict__ cntA, int* __restrict__ inclA,
                           int* __restrict__ bsumA, const int* __restrict__ cntB,
                           int* __restrict__ inclB, int* __restrict__ bsumB) {
    __shared__ int sh[1024];
    int tid = threadIdx.x;
    int i = blockIdx.x * 1024 + tid;
    sh[tid] = (i < NN) ? cntA[i] : 0;
    __syncthreads();
    block_incl_scan(sh, tid);
    if (i < NN) inclA[i] = sh[tid];
    if (tid == 1023) bsumA[blockIdx.x] = sh[1023];
    __syncthreads();
    sh[tid] = (i < NN) ? cntB[i] : 0;
    __syncthreads();
    block_incl_scan(sh, tid);
    if (i < NN) inclB[i] = sh[tid];
    if (tid == 1023) bsumB[blockIdx.x] = sh[1023];
}

__global__ void scan_mid_k() {
    __shared__ int sh[128];
    __shared__ int orig[128];
    int tid = threadIdx.x;
#pragma unroll
    for (int pass = 0; pass < 2; pass++) {
        int* bsum = pass ? g_bsumC : g_bsumR;
        int v = (tid < NB) ? bsum[tid] : 0;
        sh[tid] = v;
        orig[tid] = v;
        __syncthreads();
#pragma unroll
        for (int off = 1; off < 128; off <<= 1) {
            int t = (tid >= off) ? sh[tid - off] : 0;
            __syncthreads();
            sh[tid] += t;
            __syncthreads();
        }
        if (tid < NB) bsum[tid] = sh[tid] - orig[tid];
        __syncthreads();
    }
}

__global__ void scan_final(const int* __restrict__ cntA, const int* __restrict__ inclA,
                           const int* __restrict__ bsumA, int* __restrict__ startA,
                           int* __restrict__ curA, const int* __restrict__ cntB,
                           const int* __restrict__ inclB, const int* __restrict__ bsumB,
                           int* __restrict__ startB, int* __restrict__ curB) {
    int i = blockIdx.x * 1024 + threadIdx.x;
    if (i >= NN) return;
    int blk = blockIdx.x;
    int eA = bsumA[blk] + inclA[i] - cntA[i];
    startA[i] = eA;
    curA[i] = eA;
    int eB = bsumB[blk] + inclB[i] - cntB[i];
    startB[i] = eB;
    curB[i] = eB;
    if (i == 0) { startA[NN] = EE; startB[NN] = EE; }
}

__global__ void scatter_e(const int* __restrict__ row, const int* __restrict__ col) {
    int e = blockIdx.x * blockDim.x + threadIdx.x;
    if (e >= EE) return;
    int r = row[e], c = col[e];
    int p1 = atomicAdd(&g_curR[r], 1);
    g_col[p1] = c;
    int p2 = atomicAdd(&g_curC[c], 1);
    g_crow[p2] = r;
    g_cpidx[p2] = p1;
}

// ---------------- per-node attention scores (all 3 blocks) ----------------
__global__ void s12_k(const float* __restrict__ x, const float* __restrict__ att) {
    int t = blockIdx.x * blockDim.x + threadIdx.x;
    int u = t >> 5, lane = t & 31;
    if (u >= NN) return;
    float4 xv = *(const float4*)&x[u * 128 + lane * 4];
#pragma unroll
    for (int b = 0; b < 3; b++) {
        float4 a1 = *(const float4*)&att[b * 256 + lane * 4];
        float4 a2 = *(const float4*)&att[b * 256 + 128 + lane * 4];
        float d1 = xv.x * a1.x + xv.y * a1.y + xv.z * a1.z + xv.w * a1.w;
        float d2 = xv.x * a2.x + xv.y * a2.y + xv.z * a2.z + xv.w * a2.w;
#pragma unroll
        for (int o = 16; o > 0; o >>= 1) {
            d1 += __shfl_xor_sync(0xffffffffu, d1, o);
            d2 += __shfl_xor_sync(0xffffffffu, d2, o);
        }
        if (lane == 0) {
            g_s1[b * NN + u] = d1;
            g_s2[b * NN + u] = d2;
        }
    }
}

__device__ __forceinline__ float lrelu(float w) { return w >= 0.f ? w : NEG * w; }

// ---------------- exact segment sparsemax, all 3 blocks in one launch ----------------
__global__ void sparsemax_all_k() {
    __shared__ int   shc[8][SCAP];
    __shared__ float shz[8][SCAP];
    int lane = threadIdx.x & 31, wl = threadIdx.x >> 5;
    int u = blockIdx.x * 8 + wl;
    if (u >= NN) return;
    int st = g_startR[u], en = g_startR[u + 1];
    int d = en - st;
    if (d == 0) return;
    int* shci = shc[wl];
    float* shzi = shz[wl];
    for (int i = lane; i < d; i += 32)
        if (i < SCAP) shci[i] = g_col[st + i];
    __syncwarp();
#pragma unroll
    for (int b = 0; b < 3; b++) {
        float su = g_s1[b * NN + u];
        const float* s2b = &g_s2[b * NN];
        for (int i = lane; i < d; i += 32) {
            if (i < SCAP) shzi[i] = lrelu(su + s2b[shci[i]]);
        }
        __syncwarp();
        float kloc = 0.f, sloc = 0.f;
        for (int i = lane; i < d; i += 32) {
            float zi = (i < SCAP) ? shzi[i] : lrelu(su + s2b[g_col[st + i]]);
            float rank = 1.f, S = zi;
            for (int j = 0; j < d; j++) {
                float zj = (j < SCAP) ? shzi[j] : lrelu(su + s2b[g_col[st + j]]);
                if (zj > zi || (zj == zi && j < i)) { rank += 1.f; S += zj; }
            }
            if (1.f + rank * zi > S) { kloc += 1.f; sloc += zi; }
        }
#pragma unroll
        for (int o = 16; o > 0; o >>= 1) {
            kloc += __shfl_xor_sync(0xffffffffu, kloc, o);
            sloc += __shfl_xor_sync(0xffffffffu, sloc, o);
        }
        float tau = (sloc - 1.f) / kloc;  // k >= 1 always
        for (int i = lane; i < d; i += 32) {
            float zi = (i < SCAP) ? shzi[i] : lrelu(su + s2b[g_col[st + i]]);
            g_p[b * EE + st + i] = fmaxf(zi - tau, 0.f);
        }
        __syncwarp();
    }
}

// ---------------- dinv for all 3 blocks (CSC read once) ----------------
__global__ void dinv_all_k() {
    int t = blockIdx.x * blockDim.x + threadIdx.x;
    int v = t >> 5, lane = t & 31;
    if (v >= NN) return;
    int st = g_startC[v], d = g_startC[v + 1] - st;
    float s0 = 0.f, s1 = 0.f, s2 = 0.f;
    for (int i = lane; i < d; i += 32) {
        int pi = g_cpidx[st + i];
        s0 += g_p[pi];
        s1 += g_p[EE + pi];
        s2 += g_p[2 * EE + pi];
    }
#pragma unroll
    for (int o = 16; o > 0; o >>= 1) {
        s0 += __shfl_xor_sync(0xffffffffu, s0, o);
        s1 += __shfl_xor_sync(0xffffffffu, s1, o);
        s2 += __shfl_xor_sync(0xffffffffu, s2, o);
    }
    if (lane == 0) {
        g_dinv[v] = rsqrtf(s0 + 1.0f);
        g_dinv[NN + v] = rsqrtf(s1 + 1.0f);
        g_dinv[2 * NN + v] = rsqrtf(s2 + 1.0f);
    }
}

// ---------------- compact live edges per (block, dest): (u, dinv[u]*p) pairs ----------------
__global__ void ecoef_compact_k() {
    int t = blockIdx.x * blockDim.x + threadIdx.x;
    int v = t >> 5, lane = t & 31;
    if (v >= NN) return;
    int st = g_startC[v], d = g_startC[v + 1] - st;
#pragma unroll
    for (int b = 0; b < 3; b++) {
        int cnt = 0;
        for (int j0 = 0; j0 < d; j0 += 32) {
            int i = j0 + lane;
            int u = 0;
            float e = 0.f;
            bool live = false;
            if (i < d) {
                u = g_crow[st + i];
                float pv = g_p[(long long)b * EE + g_cpidx[st + i]];
                if (pv > 0.f) {
                    e = g_dinv[b * NN + u] * pv;
                    live = true;
                }
            }
            unsigned mask = __ballot_sync(0xffffffffu, live);
            int pos = cnt + __popc(mask & ((1u << lane) - 1u));
            if (live)
                g_ecc[(long long)b * EE + st + pos] = make_float2(__int_as_float(u), e);
            cnt += __popc(mask);
        }
        if (lane == 0) g_lcnt[b * NN + v] = cnt;
    }
}

// ---------------- fp16 HMMA GEMM, batched over blockIdx.y ----------------
// grid (782, nB). 512 threads, M=128 x N=128 tile, whole K in smem.
// Per-warp 16x16 fp32 epilogue staging (16 KB) -> 84 KB total smem -> 2 CTAs/SM.
__global__ __launch_bounds__(512) void gemm_h16_k(const float* __restrict__ Af,
                                                  const __half* __restrict__ Ah,
                                                  long long astride,
                                                  const float* __restrict__ Wbase,
                                                  __half* __restrict__ Obase,
                                                  long long ostride) {
    extern __shared__ char smem[];
    __half* Ws = (__half*)smem;                        // [128][LDH]
    __half* As = (__half*)(smem + WS_BYTES);           // [128][LDH]
    float* Est = (float*)(smem + WS_BYTES + AS_BYTES); // 16 warps x 256 floats
    int tid = threadIdx.x;
    int m0 = blockIdx.x * 128;
    int by = blockIdx.y;
    const float* W = Wbase + (long long)by * 16384;
    __half* O = Obase + (long long)by * ostride;
    const __half* Ahp = Ah ? (Ah + (long long)by * astride) : (const __half*)0;

    // stage A tile
#pragma unroll
    for (int l = 0; l < 8; l++) {
        int idx = tid + l * 512;
        int r = idx >> 5, k4 = idx & 31;
        int gm = m0 + r;
        __half2 p0 = __floats2half2_rn(0.f, 0.f), p1 = p0;
        if (gm < NN) {
            if (Ahp) {
                const __half2* ap = (const __half2*)&Ahp[(long long)gm * 128 + k4 * 4];
                p0 = ap[0];
                p1 = ap[1];
            } else {
                float4 v = *(const float4*)&Af[(long long)gm * 128 + k4 * 4];
                p0 = __floats2half2_rn(v.x, v.y);
                p1 = __floats2half2_rn(v.z, v.w);
            }
        }
        __half2* dst = (__half2*)&As[r * LDH + k4 * 4];
        dst[0] = p0;
        dst[1] = p1;
    }
    // stage W tile
#pragma unroll
    for (int l = 0; l < 8; l++) {
        int idx = tid + l * 512;
        int r = idx >> 5, c4 = idx & 31;
        float4 v = *(const float4*)&W[r * 128 + c4 * 4];
        __half2* dst = (__half2*)&Ws[r * LDH + c4 * 4];
        dst[0] = __floats2half2_rn(v.x, v.y);
        dst[1] = __floats2half2_rn(v.z, v.w);
    }
    __syncthreads();

    int warp = tid >> 5;
    int lane = tid & 31;
    int mi = warp & 7;
    int nh = (warp >> 3) * 64;
    int gm = m0 + mi * 16;

    wmma::fragment<wmma::accumulator, 16, 16, 16, float> acc[4];
#pragma unroll
    for (int t = 0; t < 4; t++) wmma::fill_fragment(acc[t], 0.f);
#pragma unroll
    for (int k = 0; k < 128; k += 16) {
        wmma::fragment<wmma::matrix_a, 16, 16, 16, __half, wmma::row_major> af;
        wmma::load_matrix_sync(af, As + mi * 16 * LDH + k, LDH);
#pragma unroll
        for (int t = 0; t < 4; t++) {
            wmma::fragment<wmma::matrix_b, 16, 16, 16, __half, wmma::row_major> bf;
            wmma::load_matrix_sync(bf, Ws + k * LDH + nh + t * 16, LDH);
            wmma::mma_sync(acc[t], af, bf, acc[t]);
        }
    }

    // per-warp epilogue: frag -> warp-private smem slab -> fp16 global (no block sync)
    float* wst = Est + warp * 256;
    int r = lane >> 1, c8 = (lane & 1) * 8;
    int gr = gm + r;
#pragma unroll
    for (int t = 0; t < 4; t++) {
        wmma::store_matrix_sync(wst, acc[t], 16, wmma::mem_row_major);
        __syncwarp();
        float4 v0 = *(const float4*)&wst[r * 16 + c8];
        float4 v1 = *(const float4*)&wst[r * 16 + c8 + 4];
        if (gr < NN) {
            __half2* op = (__half2*)&O[(long long)gr * 128 + nh + t * 16 + c8];
            op[0] = __floats2half2_rn(v0.x, v0.y);
            op[1] = __floats2half2_rn(v0.z, v0.w);
            op[2] = __floats2half2_rn(v1.x, v1.y);
            op[3] = __floats2half2_rn(v1.z, v1.w);
        }
        __syncwarp();
    }
}

// ---------------- GCN aggregation, batched over blockIdx.y ----------------
__global__ void gather_conv_k(const __half* __restrict__ hbase,
                              const float* __restrict__ biasbase,
                              __half* __restrict__ outbase) {
    int b = blockIdx.y;
    const __half* h = hbase + (long long)b * NNL * 128;
    __half* out = outbase + (long long)b * NNL * 128;
    const float* bias = biasbase + b * 128;
    const float2* ecc = g_ecc + (long long)b * EE;
    const int* lcnt = g_lcnt + b * NN;
    const float* dinv = g_dinv + b * NN;

    int t = blockIdx.x * blockDim.x + threadIdx.x;
    int v = t >> 5, lane = t & 31;
    if (v >= NN) return;
    int st = g_startC[v];
    int cnt = lcnt[v];
    float4 acc = make_float4(0.f, 0.f, 0.f, 0.f);
    for (int j0 = 0; j0 < cnt; j0 += 32) {
        int i = j0 + lane;
        float2 pr = make_float2(0.f, 0.f);
        if (i < cnt) pr = ecc[st + i];
        int lim = min(32, cnt - j0);
        for (int j = 0; j < lim; j++) {
            float cj = __shfl_sync(0xffffffffu, pr.y, j);
            int uj = __float_as_int(__shfl_sync(0xffffffffu, pr.x, j));
            const __half2* hp = (const __half2*)&h[(long long)uj * 128 + lane * 4];
            float2 lo = __half22float2(hp[0]);
            float2 hi = __half22float2(hp[1]);
            acc.x += cj * lo.x; acc.y += cj * lo.y;
            acc.z += cj * hi.x; acc.w += cj * hi.y;
        }
    }
    float dv = dinv[v];
    const __half2* sp = (const __half2*)&h[(long long)v * 128 + lane * 4];
    float2 slo = __half22float2(sp[0]);
    float2 shi = __half22float2(sp[1]);
    float4 bv = *(const float4*)&bias[lane * 4];
    float ox = fmaxf(bv.x + dv * (acc.x + dv * slo.x), 0.f);
    float oy = fmaxf(bv.y + dv * (acc.y + dv * slo.y), 0.f);
    float oz = fmaxf(bv.z + dv * (acc.z + dv * shi.x), 0.f);
    float ow = fmaxf(bv.w + dv * (acc.w + dv * shi.y), 0.f);
    __half2* op = (__half2*)&out[(long long)v * 128 + lane * 4];
    op[0] = __floats2half2_rn(ox, oy);
    op[1] = __floats2half2_rn(oz, ow);
}

// ---------------- pooling, batched over blockIdx.y ----------------
__global__ void hist_batch_k(const int* __restrict__ batch) {
    int i = blockIdx.x * blockDim.x + threadIdx.x;
    if (i < NN) atomicAdd(&g_cntg[batch[i]], 1);
}

__global__ void pool_k(const __half* __restrict__ zbase, const int* __restrict__ batch) {
    int b = blockIdx.y;
    const __half* z = zbase + (long long)b * NNL * 128;
    int boff = b * 256;
    int f = threadIdx.x;  // 128 threads = one feature each
    int n0 = blockIdx.x * 256;
    if (n0 >= NN) return;
    int nend = min(n0 + 256, NN);
    int cur = batch[n0];
    float ls = 0.f, lm = 0.f;
    for (int n = n0; n < nend; n++) {
        int g = batch[n];
        if (g != cur) {
            atomicAdd(&g_feats[cur * F6 + boff + f], ls);
            atomicMax((int*)&g_feats[cur * F6 + boff + 128 + f], __float_as_int(lm));
            ls = 0.f; lm = 0.f; cur = g;
        }
        float v = __half2float(z[(long long)n * 128 + f]);  // already relu'd (>= 0)
        ls += v;
        lm = fmaxf(lm, v);
    }
    atomicAdd(&g_feats[cur * F6 + boff + f], ls);
    atomicMax((int*)&g_feats[cur * F6 + boff + 128 + f], __float_as_int(lm));
}

__global__ void finalize_mean_k() {
    int i = blockIdx.x * blockDim.x + threadIdx.x;
    if (i >= GG * 384) return;
    int g = i / 384, r = i % 384;
    int b = r >> 7, f = r & 127;
    float c = (float)max(g_cntg[g], 1);
    g_feats[g * F6 + b * 256 + f] /= c;
}

// ---------------- tiny MLP head ----------------
__global__ void mlp1_k(const float* __restrict__ w, const float* __restrict__ bias) {
    __shared__ float sh[F6];
    int g = blockIdx.x, j = threadIdx.x;  // 256 threads
    for (int i = j; i < F6; i += 256) sh[i] = g_feats[g * F6 + i];
    __syncthreads();
    float acc = bias[j];
#pragma unroll 8
    for (int i = 0; i < F6; i++) acc += sh[i] * w[i * 256 + j];
    g_mlp1[g * 256 + j] = fmaxf(acc, 0.f);
}

__global__ void mlp2_k(const float* __restrict__ w, const float* __restrict__ bias) {
    __shared__ float sh[256];
    int g = blockIdx.x, j = threadIdx.x;  // 128 threads
    for (int i = j; i < 256; i += 128) sh[i] = g_mlp1[g * 256 + i];
    __syncthreads();
    float acc = bias[j];
#pragma unroll 8
    for (int i = 0; i < 256; i++) acc += sh[i] * w[i * 128 + j];
    g_mlp2[g * 128 + j] = fmaxf(acc, 0.f);
}

__global__ void mlp3_k(const float* __restrict__ w, const float* __restrict__ bias,
                       float* __restrict__ out) {
    int g = blockIdx.x, lane = threadIdx.x;  // 32 threads
    __shared__ float sh[128];
    for (int i = lane; i < 128; i += 32) sh[i] = g_mlp2[g * 128 + i];
    __syncwarp();
    float acc[NCLS];
#pragma unroll
    for (int c = 0; c < NCLS; c++) acc[c] = 0.f;
    for (int i = lane; i < 128; i += 32) {
        float v = sh[i];
#pragma unroll
        for (int c = 0; c < NCLS; c++) acc[c] += v * w[i * NCLS + c];
    }
#pragma unroll
    for (int c = 0; c < NCLS; c++)
#pragma unroll
        for (int o = 16; o > 0; o >>= 1) acc[c] += __shfl_xor_sync(0xffffffffu, acc[c], o);
    if (lane == 0) {
        float vals[NCLS], m = -1e30f;
        for (int c = 0; c < NCLS; c++) { vals[c] = acc[c] + bias[c]; m = fmaxf(m, vals[c]); }
        float s = 0.f;
        for (int c = 0; c < NCLS; c++) s += expf(vals[c] - m);
        float lse = logf(s);
        for (int c = 0; c < NCLS; c++) out[g * NCLS + c] = vals[c] - m - lse;
    }
}

// ---------------- host launch ----------------
extern "C" void kernel_launch(void* const* d_in, const int* in_sizes, int n_in,
                              void* d_out, int out_size) {
    const float* x = (const float*)d_in[0];
    const int* ei = (const int*)d_in[1];
    // d_in[2] = edge_attr: unused by the reference
    const int* batch = (const int*)d_in[3];
    int pi = (n_in >= 16) ? 5 : 4;
    const float* att  = (const float*)d_in[pi + 0];
    const float* W1   = (const float*)d_in[pi + 1];
    const float* b1   = (const float*)d_in[pi + 2];
    const float* W2   = (const float*)d_in[pi + 3];
    const float* b2   = (const float*)d_in[pi + 4];
    const float* fc1w = (const float*)d_in[pi + 5];
    const float* fc1b = (const float*)d_in[pi + 6];
    const float* fc2w = (const float*)d_in[pi + 7];
    const float* fc2b = (const float*)d_in[pi + 8];
    const float* fc3w = (const float*)d_in[pi + 9];
    const float* fc3b = (const float*)d_in[pi + 10];
    float* out = (float*)d_out;

    float* feats;
    __half *h16A, *h16B, *h16C;
    int *cntR, *cntC, *startR, *startC, *curR, *curC;
    int *inclR, *inclC, *bsumR, *bsumC, *cntg;
    cudaGetSymbolAddress((void**)&h16A, g_h16A);
    cudaGetSymbolAddress((void**)&h16B, g_h16B);
    cudaGetSymbolAddress((void**)&h16C, g_h16C);
    cudaGetSymbolAddress((void**)&feats, g_feats);
    cudaGetSymbolAddress((void**)&cntR, g_cntR);
    cudaGetSymbolAddress((void**)&cntC, g_cntC);
    cudaGetSymbolAddress((void**)&startR, g_startR);
    cudaGetSymbolAddress((void**)&startC, g_startC);
    cudaGetSymbolAddress((void**)&curR, g_curR);
    cudaGetSymbolAddress((void**)&curC, g_curC);
    cudaGetSymbolAddress((void**)&inclR, g_inclR);
    cudaGetSymbolAddress((void**)&inclC, g_inclC);
    cudaGetSymbolAddress((void**)&bsumR, g_bsumR);
    cudaGetSymbolAddress((void**)&bsumC, g_bsumC);
    cudaGetSymbolAddress((void**)&cntg, g_cntg);

    cudaFuncSetAttribute(gemm_h16_k, cudaFuncAttributeMaxDynamicSharedMemorySize,
                         GEMM_SMEM_BYTES);

    const int* row = ei;
    const int* col = ei + EE;

    // async zeroing (graph-capturable memset nodes, no kernel launches)
    cudaMemsetAsync(cntR, 0, NN * sizeof(int));
    cudaMemsetAsync(cntC, 0, NN * sizeof(int));
    cudaMemsetAsync(cntg, 0, GG * sizeof(int));
    cudaMemsetAsync(feats, 0, GG * F6 * sizeof(float));

    // CSR/CSC build; batched conv1 GEMM at launch slot 4 for the ncu capture.
    hist_e<<<cdiv(EE, 256), 256>>>(row, col);                                   // 1
    scan_local<<<NB, 1024>>>(cntR, inclR, bsumR, cntC, inclC, bsumC);           // 2
    scan_mid_k<<<1, 128>>>();                                                   // 3
    gemm_h16_k<<<dim3(cdiv(NN, 128), 3), 512, GEMM_SMEM_BYTES>>>(               // 4
        x, (const __half*)0, 0ll, W1, h16A, NNL * 128);
    scan_final<<<NB, 1024>>>(cntR, inclR, bsumR, startR, curR,                  // 5
                             cntC, inclC, bsumC, startC, curC);
    scatter_e<<<cdiv(EE, 256), 256>>>(row, col);                                // 6

    // attention scores + per-graph counts
    s12_k<<<cdiv(NN * 32, 256), 256>>>(x, att);
    hist_batch_k<<<cdiv(NN, 256), 256>>>(batch);

    // edge weights for all 3 blocks
    sparsemax_all_k<<<cdiv(NN, 8), 256>>>();
    dinv_all_k<<<cdiv(NN * 32, 256), 256>>>();
    ecoef_compact_k<<<cdiv(NN * 32, 256), 256>>>();

    // all 3 blocks batched via gridDim.y
    gather_conv_k<<<dim3(cdiv(NN * 32, 256), 3), 256>>>(h16A, b1, h16B);
    gemm_h16_k<<<dim3(cdiv(NN, 128), 3), 512, GEMM_SMEM_BYTES>>>(
        (const float*)0, h16B, NNL * 128, W2, h16C, NNL * 128);
    gather_conv_k<<<dim3(cdiv(NN * 32, 256), 3), 256>>>(h16C, b2, h16A);
    pool_k<<<dim3(cdiv(NN, 256), 3), 128>>>(h16A, batch);

    finalize_mean_k<<<cdiv(GG * 384, 256), 256>>>();
    mlp1_k<<<GG, 256>>>(fc1w, fc1b);
    mlp2_k<<<GG, 128>>>(fc2w, fc2b);
    mlp3_k<<<GG, 32>>>(fc3w, fc3b, out);

    (void)in_sizes;
    (void)out_size;
}

// round 15
// speedup vs baseline: 1.0764x; 1.0764x over previous
#include <cuda_runtime.h>
#include <cuda_fp16.h>
#include <mma.h>
#include <math.h>

using namespace nvcuda;

#define NN 100000
#define EE 1600000
#define GG 256
#define NCLS 10
#define F6 768
#define SCAP 192
#define NEG 0.2f
#define NB 98  // cdiv(NN, 1024)
#define NNL ((long long)NN)

#define LDH 136  // half-element leading dim for A/W smem tiles
#define WS_BYTES (128 * LDH * 2)
#define AS_BYTES (128 * LDH * 2)
#define EST_BYTES (128 * 128 * 4)  // block-wide fp32 epilogue staging (R13 proven)
#define GEMM_SMEM_BYTES (WS_BYTES + AS_BYTES + EST_BYTES)

static inline int cdiv(int a, int b) { return (a + b - 1) / b; }

// ---------------- device scratch (no allocations allowed) ----------------
__device__ int    g_cntR[NN];
__device__ int    g_cntC[NN];
__device__ int    g_startR[NN + 1];
__device__ int    g_startC[NN + 1];
__device__ int    g_curR[NN];
__device__ int    g_curC[NN];
__device__ int    g_inclR[NN];
__device__ int    g_inclC[NN];
__device__ int    g_bsumR[NB];
__device__ int    g_bsumC[NB];
__device__ int    g_col[EE];        // CSR (by source): dest of each slot
__device__ int    g_crow[EE];       // CSC (by dest): source of each slot
__device__ int    g_cpidx[EE];      // CSC slot -> CSR slot
__device__ float  g_p[3 * EE];      // sparsemax weights, CSR order, per block
__device__ __align__(16) float2 g_ecc[3ll * EE];  // compacted live edges (u, ec)
__device__ int    g_lcnt[3 * NN];   // live-edge count per (block, dest)
__device__ float  g_s1[3 * NN];
__device__ float  g_s2[3 * NN];
__device__ float  g_dinv[3 * NN];
__device__ __align__(16) __half g_h16A[3ll * NN * 128];  // conv1 gemm out / conv2 gather out
__device__ __align__(16) __half g_h16B[3ll * NN * 128];  // conv1 gather out (gemm2 in)
__device__ __align__(16) __half g_h16C[3ll * NN * 128];  // conv2 gemm out
__device__ float  g_feats[GG * F6];
__device__ float  g_mlp1[GG * 256];
__device__ float  g_mlp2[GG * 128];
__device__ int    g_cntg[GG];

// ---------------- CSR + CSC build ----------------
__global__ void hist_e(const int* __restrict__ row, const int* __restrict__ col) {
    int e = blockIdx.x * blockDim.x + threadIdx.x;
    if (e >= EE) return;
    atomicAdd(&g_cntR[row[e]], 1);
    atomicAdd(&g_cntC[col[e]], 1);
}

__device__ __forceinline__ void block_incl_scan(int* sh, int tid) {
#pragma unroll
    for (int off = 1; off < 1024; off <<= 1) {
        int t = (tid >= off) ? sh[tid - off] : 0;
        __syncthreads();
        sh[tid] += t;
        __syncthreads();
    }
}

__global__ void scan_local(const int* __restrict__ cntA, int* __restrict__ inclA,
                           int* __restrict__ bsumA, const int* __restrict__ cntB,
                           int* __restrict__ inclB, int* __restrict__ bsumB) {
    __shared__ int sh[1024];
    int tid = threadIdx.x;
    int i = blockIdx.x * 1024 + tid;
    sh[tid] = (i < NN) ? cntA[i] : 0;
    __syncthreads();
    block_incl_scan(sh, tid);
    if (i < NN) inclA[i] = sh[tid];
    if (tid == 1023) bsumA[blockIdx.x] = sh[1023];
    __syncthreads();
    sh[tid] = (i < NN) ? cntB[i] : 0;
    __syncthreads();
    block_incl_scan(sh, tid);
    if (i < NN) inclB[i] = sh[tid];
    if (tid == 1023) bsumB[blockIdx.x] = sh[1023];
}

__global__ void scan_mid_k() {
    __shared__ int sh[128];
    __shared__ int orig[128];
    int tid = threadIdx.x;
#pragma unroll
    for (int pass = 0; pass < 2; pass++) {
        int* bsum = pass ? g_bsumC : g_bsumR;
        int v = (tid < NB) ? bsum[tid] : 0;
        sh[tid] = v;
        orig[tid] = v;
        __syncthreads();
#pragma unroll
        for (int off = 1; off < 128; off <<= 1) {
            int t = (tid >= off) ? sh[tid - off] : 0;
            __syncthreads();
            sh[tid] += t;
            __syncthreads();
        }
        if (tid < NB) bsum[tid] = sh[tid] - orig[tid];
        __syncthreads();
    }
}

__global__ void scan_final(const int* __restrict__ cntA, const int* __restrict__ inclA,
                           const int* __restrict__ bsumA, int* __restrict__ startA,
                           int* __restrict__ curA, const int* __restrict__ cntB,
                           const int* __restrict__ inclB, const int* __restrict__ bsumB,
                           int* __restrict__ startB, int* __restrict__ curB) {
    int i = blockIdx.x * 1024 + threadIdx.x;
    if (i >= NN) return;
    int blk = blockIdx.x;
    int eA = bsumA[blk] + inclA[i] - cntA[i];
    startA[i] = eA;
    curA[i] = eA;
    int eB = bsumB[blk] + inclB[i] - cntB[i];
    startB[i] = eB;
    curB[i] = eB;
    if (i == 0) { startA[NN] = EE; startB[NN] = EE; }
}

__global__ void scatter_e(const int* __restrict__ row, const int* __restrict__ col) {
    int e = blockIdx.x * blockDim.x + threadIdx.x;
    if (e >= EE) return;
    int r = row[e], c = col[e];
    int p1 = atomicAdd(&g_curR[r], 1);
    g_col[p1] = c;
    int p2 = atomicAdd(&g_curC[c], 1);
    g_crow[p2] = r;
    g_cpidx[p2] = p1;
}

// ---------------- per-node attention scores (all 3 blocks) ----------------
__global__ void s12_k(const float* __restrict__ x, const float* __restrict__ att) {
    int t = blockIdx.x * blockDim.x + threadIdx.x;
    int u = t >> 5, lane = t & 31;
    if (u >= NN) return;
    float4 xv = *(const float4*)&x[u * 128 + lane * 4];
#pragma unroll
    for (int b = 0; b < 3; b++) {
        float4 a1 = *(const float4*)&att[b * 256 + lane * 4];
        float4 a2 = *(const float4*)&att[b * 256 + 128 + lane * 4];
        float d1 = xv.x * a1.x + xv.y * a1.y + xv.z * a1.z + xv.w * a1.w;
        float d2 = xv.x * a2.x + xv.y * a2.y + xv.z * a2.z + xv.w * a2.w;
#pragma unroll
        for (int o = 16; o > 0; o >>= 1) {
            d1 += __shfl_xor_sync(0xffffffffu, d1, o);
            d2 += __shfl_xor_sync(0xffffffffu, d2, o);
        }
        if (lane == 0) {
            g_s1[b * NN + u] = d1;
            g_s2[b * NN + u] = d2;
        }
    }
}

__device__ __forceinline__ float lrelu(float w) { return w >= 0.f ? w : NEG * w; }

// ---------------- exact segment sparsemax, all 3 blocks in one launch ----------------
__global__ void sparsemax_all_k() {
    __shared__ int   shc[8][SCAP];
    __shared__ float shz[8][SCAP];
    int lane = threadIdx.x & 31, wl = threadIdx.x >> 5;
    int u = blockIdx.x * 8 + wl;
    if (u >= NN) return;
    int st = g_startR[u], en = g_startR[u + 1];
    int d = en - st;
    if (d == 0) return;
    int* shci = shc[wl];
    float* shzi = shz[wl];
    for (int i = lane; i < d; i += 32)
        if (i < SCAP) shci[i] = g_col[st + i];
    __syncwarp();
#pragma unroll
    for (int b = 0; b < 3; b++) {
        float su = g_s1[b * NN + u];
        const float* s2b = &g_s2[b * NN];
        for (int i = lane; i < d; i += 32) {
            if (i < SCAP) shzi[i] = lrelu(su + s2b[shci[i]]);
        }
        __syncwarp();
        float kloc = 0.f, sloc = 0.f;
        for (int i = lane; i < d; i += 32) {
            float zi = (i < SCAP) ? shzi[i] : lrelu(su + s2b[g_col[st + i]]);
            float rank = 1.f, S = zi;
            for (int j = 0; j < d; j++) {
                float zj = (j < SCAP) ? shzi[j] : lrelu(su + s2b[g_col[st + j]]);
                if (zj > zi || (zj == zi && j < i)) { rank += 1.f; S += zj; }
            }
            if (1.f + rank * zi > S) { kloc += 1.f; sloc += zi; }
        }
#pragma unroll
        for (int o = 16; o > 0; o >>= 1) {
            kloc += __shfl_xor_sync(0xffffffffu, kloc, o);
            sloc += __shfl_xor_sync(0xffffffffu, sloc, o);
        }
        float tau = (sloc - 1.f) / kloc;  // k >= 1 always
        for (int i = lane; i < d; i += 32) {
            float zi = (i < SCAP) ? shzi[i] : lrelu(su + s2b[g_col[st + i]]);
            g_p[b * EE + st + i] = fmaxf(zi - tau, 0.f);
        }
        __syncwarp();
    }
}

// ---------------- dinv for all 3 blocks (CSC read once) ----------------
__global__ void dinv_all_k() {
    int t = blockIdx.x * blockDim.x + threadIdx.x;
    int v = t >> 5, lane = t & 31;
    if (v >= NN) return;
    int st = g_startC[v], d = g_startC[v + 1] - st;
    float s0 = 0.f, s1 = 0.f, s2 = 0.f;
    for (int i = lane; i < d; i += 32) {
        int pi = g_cpidx[st + i];
        s0 += g_p[pi];
        s1 += g_p[EE + pi];
        s2 += g_p[2 * EE + pi];
    }
#pragma unroll
    for (int o = 16; o > 0; o >>= 1) {
        s0 += __shfl_xor_sync(0xffffffffu, s0, o);
        s1 += __shfl_xor_sync(0xffffffffu, s1, o);
        s2 += __shfl_xor_sync(0xffffffffu, s2, o);
    }
    if (lane == 0) {
        g_dinv[v] = rsqrtf(s0 + 1.0f);
        g_dinv[NN + v] = rsqrtf(s1 + 1.0f);
        g_dinv[2 * NN + v] = rsqrtf(s2 + 1.0f);
    }
}

// ---------------- compact live edges per (block, dest): (u, dinv[u]*p) pairs ----------------
__global__ void ecoef_compact_k() {
    int t = blockIdx.x * blockDim.x + threadIdx.x;
    int v = t >> 5, lane = t & 31;
    if (v >= NN) return;
    int st = g_startC[v], d = g_startC[v + 1] - st;
#pragma unroll
    for (int b = 0; b < 3; b++) {
        int cnt = 0;
        for (int j0 = 0; j0 < d; j0 += 32) {
            int i = j0 + lane;
            int u = 0;
            float e = 0.f;
            bool live = false;
            if (i < d) {
                u = g_crow[st + i];
                float pv = g_p[(long long)b * EE + g_cpidx[st + i]];
                if (pv > 0.f) {
                    e = g_dinv[b * NN + u] * pv;
                    live = true;
                }
            }
            unsigned mask = __ballot_sync(0xffffffffu, live);
            int pos = cnt + __popc(mask & ((1u << lane) - 1u));
            if (live)
                g_ecc[(long long)b * EE + st + pos] = make_float2(__int_as_float(u), e);
            cnt += __popc(mask);
        }
        if (lane == 0) g_lcnt[b * NN + v] = cnt;
    }
}

// ---------------- fp16 HMMA GEMM, batched over blockIdx.y (R13 proven config) ----------------
__global__ __launch_bounds__(512) void gemm_h16_k(const float* __restrict__ Af,
                                                  const __half* __restrict__ Ah,
                                                  long long astride,
                                                  const float* __restrict__ Wbase,
                                                  __half* __restrict__ Obase,
                                                  long long ostride) {
    extern __shared__ char smem[];
    __half* Ws = (__half*)smem;                        // [128][LDH]
    __half* As = (__half*)(smem + WS_BYTES);           // [128][LDH]
    float* Est = (float*)(smem + WS_BYTES + AS_BYTES); // [128][128]
    int tid = threadIdx.x;
    int m0 = blockIdx.x * 128;
    int by = blockIdx.y;
    const float* W = Wbase + (long long)by * 16384;
    __half* O = Obase + (long long)by * ostride;
    const __half* Ahp = Ah ? (Ah + (long long)by * astride) : (const __half*)0;

    // stage A tile
#pragma unroll
    for (int l = 0; l < 8; l++) {
        int idx = tid + l * 512;
        int r = idx >> 5, k4 = idx & 31;
        int gm = m0 + r;
        __half2 p0 = __floats2half2_rn(0.f, 0.f), p1 = p0;
        if (gm < NN) {
            if (Ahp) {
                const __half2* ap = (const __half2*)&Ahp[(long long)gm * 128 + k4 * 4];
                p0 = ap[0];
                p1 = ap[1];
            } else {
                float4 v = *(const float4*)&Af[(long long)gm * 128 + k4 * 4];
                p0 = __floats2half2_rn(v.x, v.y);
                p1 = __floats2half2_rn(v.z, v.w);
            }
        }
        __half2* dst = (__half2*)&As[r * LDH + k4 * 4];
        dst[0] = p0;
        dst[1] = p1;
    }
    // stage W tile
#pragma unroll
    for (int l = 0; l < 8; l++) {
        int idx = tid + l * 512;
        int r = idx >> 5, c4 = idx & 31;
        float4 v = *(const float4*)&W[r * 128 + c4 * 4];
        __half2* dst = (__half2*)&Ws[r * LDH + c4 * 4];
        dst[0] = __floats2half2_rn(v.x, v.y);
        dst[1] = __floats2half2_rn(v.z, v.w);
    }
    __syncthreads();

    int warp = tid >> 5;
    int mi = warp & 7;
    int nh = (warp >> 3) * 64;
    int gm = m0 + mi * 16;

    wmma::fragment<wmma::accumulator, 16, 16, 16, float> acc[4];
#pragma unroll
    for (int t = 0; t < 4; t++) wmma::fill_fragment(acc[t], 0.f);
#pragma unroll
    for (int k = 0; k < 128; k += 16) {
        wmma::fragment<wmma::matrix_a, 16, 16, 16, __half, wmma::row_major> af;
        wmma::load_matrix_sync(af, As + mi * 16 * LDH + k, LDH);
#pragma unroll
        for (int t = 0; t < 4; t++) {
            wmma::fragment<wmma::matrix_b, 16, 16, 16, __half, wmma::row_major> bf;
            wmma::load_matrix_sync(bf, Ws + k * LDH + nh + t * 16, LDH);
            wmma::mma_sync(acc[t], af, bf, acc[t]);
        }
    }

    // epilogue: acc -> Est (fp32, block-wide, conflict-free) -> fp16 global
#pragma unroll
    for (int t = 0; t < 4; t++)
        wmma::store_matrix_sync(Est + mi * 16 * 128 + nh + t * 16, acc[t], 128,
                                wmma::mem_row_major);
    __syncthreads();
#pragma unroll
    for (int l = 0; l < 8; l++) {
        int idx = tid + l * 512;
        int r = idx >> 5, c4 = idx & 31;
        int gr = m0 + r;
        if (gr < NN) {
            float4 vv = *(const float4*)&Est[r * 128 + c4 * 4];
            __half2* op = (__half2*)&O[(long long)gr * 128 + c4 * 4];
            op[0] = __floats2half2_rn(vv.x, vv.y);
            op[1] = __floats2half2_rn(vv.z, vv.w);
        }
    }
}

// ---------------- GCN aggregation, batched over blockIdx.y ----------------
__global__ void gather_conv_k(const __half* __restrict__ hbase,
                              const float* __restrict__ biasbase,
                              __half* __restrict__ outbase) {
    int b = blockIdx.y;
    const __half* h = hbase + (long long)b * NNL * 128;
    __half* out = outbase + (long long)b * NNL * 128;
    const float* bias = biasbase + b * 128;
    const float2* ecc = g_ecc + (long long)b * EE;
    const int* lcnt = g_lcnt + b * NN;
    const float* dinv = g_dinv + b * NN;

    int t = blockIdx.x * blockDim.x + threadIdx.x;
    int v = t >> 5, lane = t & 31;
    if (v >= NN) return;
    int st = g_startC[v];
    int cnt = lcnt[v];
    float4 acc = make_float4(0.f, 0.f, 0.f, 0.f);
    for (int j0 = 0; j0 < cnt; j0 += 32) {
        int i = j0 + lane;
        float2 pr = make_float2(0.f, 0.f);
        if (i < cnt) pr = ecc[st + i];
        int lim = min(32, cnt - j0);
        for (int j = 0; j < lim; j++) {
            float cj = __shfl_sync(0xffffffffu, pr.y, j);
            int uj = __float_as_int(__shfl_sync(0xffffffffu, pr.x, j));
            const __half2* hp = (const __half2*)&h[(long long)uj * 128 + lane * 4];
            float2 lo = __half22float2(hp[0]);
            float2 hi = __half22float2(hp[1]);
            acc.x += cj * lo.x; acc.y += cj * lo.y;
            acc.z += cj * hi.x; acc.w += cj * hi.y;
        }
    }
    float dv = dinv[v];
    const __half2* sp = (const __half2*)&h[(long long)v * 128 + lane * 4];
    float2 slo = __half22float2(sp[0]);
    float2 shi = __half22float2(sp[1]);
    float4 bv = *(const float4*)&bias[lane * 4];
    float ox = fmaxf(bv.x + dv * (acc.x + dv * slo.x), 0.f);
    float oy = fmaxf(bv.y + dv * (acc.y + dv * slo.y), 0.f);
    float oz = fmaxf(bv.z + dv * (acc.z + dv * shi.x), 0.f);
    float ow = fmaxf(bv.w + dv * (acc.w + dv * shi.y), 0.f);
    __half2* op = (__half2*)&out[(long long)v * 128 + lane * 4];
    op[0] = __floats2half2_rn(ox, oy);
    op[1] = __floats2half2_rn(oz, ow);
}

// ---------------- pooling, batched over blockIdx.y ----------------
__global__ void hist_batch_k(const int* __restrict__ batch) {
    int i = blockIdx.x * blockDim.x + threadIdx.x;
    if (i < NN) atomicAdd(&g_cntg[batch[i]], 1);
}

__global__ void pool_k(const __half* __restrict__ zbase, const int* __restrict__ batch) {
    int b = blockIdx.y;
    const __half* z = zbase + (long long)b * NNL * 128;
    int boff = b * 256;
    int f = threadIdx.x;  // 128 threads = one feature each
    int n0 = blockIdx.x * 256;
    if (n0 >= NN) return;
    int nend = min(n0 + 256, NN);
    int cur = batch[n0];
    float ls = 0.f, lm = 0.f;
    for (int n = n0; n < nend; n++) {
        int g = batch[n];
        if (g != cur) {
            atomicAdd(&g_feats[cur * F6 + boff + f], ls);
            atomicMax((int*)&g_feats[cur * F6 + boff + 128 + f], __float_as_int(lm));
            ls = 0.f; lm = 0.f; cur = g;
        }
        float v = __half2float(z[(long long)n * 128 + f]);  // already relu'd (>= 0)
        ls += v;
        lm = fmaxf(lm, v);
    }
    atomicAdd(&g_feats[cur * F6 + boff + f], ls);
    atomicMax((int*)&g_feats[cur * F6 + boff + 128 + f], __float_as_int(lm));
}

__global__ void finalize_mean_k() {
    int i = blockIdx.x * blockDim.x + threadIdx.x;
    if (i >= GG * 384) return;
    int g = i / 384, r = i % 384;
    int b = r >> 7, f = r & 127;
    float c = (float)max(g_cntg[g], 1);
    g_feats[g * F6 + b * 256 + f] /= c;
}

// ---------------- tiny MLP head ----------------
__global__ void mlp1_k(const float* __restrict__ w, const float* __restrict__ bias) {
    __shared__ float sh[F6];
    int g = blockIdx.x, j = threadIdx.x;  // 256 threads
    for (int i = j; i < F6; i += 256) sh[i] = g_feats[g * F6 + i];
    __syncthreads();
    float acc = bias[j];
#pragma unroll 8
    for (int i = 0; i < F6; i++) acc += sh[i] * w[i * 256 + j];
    g_mlp1[g * 256 + j] = fmaxf(acc, 0.f);
}

__global__ void mlp2_k(const float* __restrict__ w, const float* __restrict__ bias) {
    __shared__ float sh[256];
    int g = blockIdx.x, j = threadIdx.x;  // 128 threads
    for (int i = j; i < 256; i += 128) sh[i] = g_mlp1[g * 256 + i];
    __syncthreads();
    float acc = bias[j];
#pragma unroll 8
    for (int i = 0; i < 256; i++) acc += sh[i] * w[i * 128 + j];
    g_mlp2[g * 128 + j] = fmaxf(acc, 0.f);
}

__global__ void mlp3_k(const float* __restrict__ w, const float* __restrict__ bias,
                       float* __restrict__ out) {
    int g = blockIdx.x, lane = threadIdx.x;  // 32 threads
    __shared__ float sh[128];
    for (int i = lane; i < 128; i += 32) sh[i] = g_mlp2[g * 128 + i];
    __syncwarp();
    float acc[NCLS];
#pragma unroll
    for (int c = 0; c < NCLS; c++) acc[c] = 0.f;
    for (int i = lane; i < 128; i += 32) {
        float v = sh[i];
#pragma unroll
        for (int c = 0; c < NCLS; c++) acc[c] += v * w[i * NCLS + c];
    }
#pragma unroll
    for (int c = 0; c < NCLS; c++)
#pragma unroll
        for (int o = 16; o > 0; o >>= 1) acc[c] += __shfl_xor_sync(0xffffffffu, acc[c], o);
    if (lane == 0) {
        float vals[NCLS], m = -1e30f;
        for (int c = 0; c < NCLS; c++) { vals[c] = acc[c] + bias[c]; m = fmaxf(m, vals[c]); }
        float s = 0.f;
        for (int c = 0; c < NCLS; c++) s += expf(vals[c] - m);
        float lse = logf(s);
        for (int c = 0; c < NCLS; c++) out[g * NCLS + c] = vals[c] - m - lse;
    }
}

// ---------------- host launch ----------------
extern "C" void kernel_launch(void* const* d_in, const int* in_sizes, int n_in,
                              void* d_out, int out_size) {
    const float* x = (const float*)d_in[0];
    const int* ei = (const int*)d_in[1];
    // d_in[2] = edge_attr: unused by the reference
    const int* batch = (const int*)d_in[3];
    int pi = (n_in >= 16) ? 5 : 4;
    const float* att  = (const float*)d_in[pi + 0];
    const float* W1   = (const float*)d_in[pi + 1];
    const float* b1   = (const float*)d_in[pi + 2];
    const float* W2   = (const float*)d_in[pi + 3];
    const float* b2   = (const float*)d_in[pi + 4];
    const float* fc1w = (const float*)d_in[pi + 5];
    const float* fc1b = (const float*)d_in[pi + 6];
    const float* fc2w = (const float*)d_in[pi + 7];
    const float* fc2b = (const float*)d_in[pi + 8];
    const float* fc3w = (const float*)d_in[pi + 9];
    const float* fc3b = (const float*)d_in[pi + 10];
    float* out = (float*)d_out;

    float* feats;
    __half *h16A, *h16B, *h16C;
    int *cntR, *cntC, *startR, *startC, *curR, *curC;
    int *inclR, *inclC, *bsumR, *bsumC, *cntg;
    cudaGetSymbolAddress((void**)&h16A, g_h16A);
    cudaGetSymbolAddress((void**)&h16B, g_h16B);
    cudaGetSymbolAddress((void**)&h16C, g_h16C);
    cudaGetSymbolAddress((void**)&feats, g_feats);
    cudaGetSymbolAddress((void**)&cntR, g_cntR);
    cudaGetSymbolAddress((void**)&cntC, g_cntC);
    cudaGetSymbolAddress((void**)&startR, g_startR);
    cudaGetSymbolAddress((void**)&startC, g_startC);
    cudaGetSymbolAddress((void**)&curR, g_curR);
    cudaGetSymbolAddress((void**)&curC, g_curC);
    cudaGetSymbolAddress((void**)&inclR, g_inclR);
    cudaGetSymbolAddress((void**)&inclC, g_inclC);
    cudaGetSymbolAddress((void**)&bsumR, g_bsumR);
    cudaGetSymbolAddress((void**)&bsumC, g_bsumC);
    cudaGetSymbolAddress((void**)&cntg, g_cntg);

    cudaFuncSetAttribute(gemm_h16_k, cudaFuncAttributeMaxDynamicSharedMemorySize,
                         GEMM_SMEM_BYTES);

    // side streams + events for capture-compatible fork/join (created once; host-side
    // resources only, no device memory; identical GPU work every call)
    static cudaStream_t sA = 0, sB = 0;
    static cudaEvent_t evRoot = 0, evA = 0, evB = 0;
    if (!sA) {
        cudaStreamCreateWithFlags(&sA, cudaStreamNonBlocking);
        cudaStreamCreateWithFlags(&sB, cudaStreamNonBlocking);
        cudaEventCreateWithFlags(&evRoot, cudaEventDisableTiming);
        cudaEventCreateWithFlags(&evA, cudaEventDisableTiming);
        cudaEventCreateWithFlags(&evB, cudaEventDisableTiming);
    }

    const int* row = ei;
    const int* col = ei + EE;

    // async zeroing on the main (capturing) stream
    cudaMemsetAsync(cntR, 0, NN * sizeof(int));
    cudaMemsetAsync(cntC, 0, NN * sizeof(int));
    cudaMemsetAsync(cntg, 0, GG * sizeof(int));
    cudaMemsetAsync(feats, 0, GG * F6 * sizeof(float));
    cudaEventRecord(evRoot, 0);

    // branch A (side stream): batched conv1 GEMM — depends only on x, W1
    cudaStreamWaitEvent(sA, evRoot, 0);
    gemm_h16_k<<<dim3(cdiv(NN, 128), 3), 512, GEMM_SMEM_BYTES, sA>>>(
        x, (const __half*)0, 0ll, W1, h16A, NNL * 128);
    cudaEventRecord(evA, sA);

    // branch B (side stream): attention scores + per-graph counts
    cudaStreamWaitEvent(sB, evRoot, 0);
    s12_k<<<cdiv(NN * 32, 256), 256, 0, sB>>>(x, att);
    hist_batch_k<<<cdiv(NN, 256), 256, 0, sB>>>(batch);
    cudaEventRecord(evB, sB);

    // main branch: CSR/CSC build
    hist_e<<<cdiv(EE, 256), 256>>>(row, col);
    scan_local<<<NB, 1024>>>(cntR, inclR, bsumR, cntC, inclC, bsumC);
    scan_mid_k<<<1, 128>>>();
    scan_final<<<NB, 1024>>>(cntR, inclR, bsumR, startR, curR,
                             cntC, inclC, bsumC, startC, curC);
    scatter_e<<<cdiv(EE, 256), 256>>>(row, col);

    // join B: sparsemax needs s1/s2 + CSR
    cudaStreamWaitEvent(0, evB, 0);
    sparsemax_all_k<<<cdiv(NN, 8), 256>>>();
    dinv_all_k<<<cdiv(NN * 32, 256), 256>>>();
    ecoef_compact_k<<<cdiv(NN * 32, 256), 256>>>();

    // join A: gathers need the conv1 GEMM output
    cudaStreamWaitEvent(0, evA, 0);
    gather_conv_k<<<dim3(cdiv(NN * 32, 256), 3), 256>>>(h16A, b1, h16B);
    gemm_h16_k<<<dim3(cdiv(NN, 128), 3), 512, GEMM_SMEM_BYTES>>>(
        (const float*)0, h16B, NNL * 128, W2, h16C, NNL * 128);
    gather_conv_k<<<dim3(cdiv(NN * 32, 256), 3), 256>>>(h16C, b2, h16A);
    pool_k<<<dim3(cdiv(NN, 256), 3), 128>>>(h16A, batch);

    finalize_mean_k<<<cdiv(GG * 384, 256), 256>>>();
    mlp1_k<<<GG, 256>>>(fc1w, fc1b);
    mlp2_k<<<GG, 128>>>(fc2w, fc2b);
    mlp3_k<<<GG, 32>>>(fc3w, fc3b, out);

    (void)in_sizes;
    (void)out_size;
}

// round 16
// speedup vs baseline: 1.0965x; 1.0187x over previous
#include <cuda_runtime.h>
#include <cuda_fp16.h>
#include <mma.h>
#include <math.h>

using namespace nvcuda;

#define NN 100000
#define EE 1600000
#define GG 256
#define NCLS 10
#define F6 768
#define SCAP 192
#define NEG 0.2f
#define NB 98  // cdiv(NN, 1024)
#define NNL ((long long)NN)

#define LDH 136  // half-element leading dim for A/W smem tiles
#define WS_BYTES (128 * LDH * 2)
#define AS_BYTES (128 * LDH * 2)
#define EST_BYTES (128 * 128 * 4)  // block-wide fp32 epilogue staging
#define GEMM_SMEM_BYTES (WS_BYTES + AS_BYTES + EST_BYTES)

static inline int cdiv(int a, int b) { return (a + b - 1) / b; }

// ---------------- device scratch (no allocations allowed) ----------------
__device__ int    g_cntR[NN];
__device__ int    g_cntC[NN];
__device__ int    g_startR[NN + 1];
__device__ int    g_startC[NN + 1];
__device__ int    g_curR[NN];
__device__ int    g_curC[NN];
__device__ int    g_inclR[NN];
__device__ int    g_inclC[NN];
__device__ int    g_bsumR[NB];
__device__ int    g_bsumC[NB];
__device__ int    g_col[EE];        // CSR (by source): dest of each slot
__device__ int    g_crow[EE];       // CSC (by dest): source of each slot
__device__ int    g_c2c[EE];        // CSR slot -> CSC slot
__device__ float  g_pc[3 * EE];     // sparsemax weights, CSC order, per block
__device__ __align__(16) float2 g_ecc[3ll * EE];  // compacted live edges (u, ec)
__device__ int    g_lcnt[3 * NN];   // live-edge count per (block, dest)
__device__ float  g_s1[3 * NN];
__device__ float  g_s2[3 * NN];
__device__ float  g_dinv[3 * NN];
__device__ __align__(16) __half g_h16A[3ll * NN * 128];  // conv1 gemm out / conv2 gather out
__device__ __align__(16) __half g_h16B[3ll * NN * 128];  // conv1 gather out (gemm2 in)
__device__ __align__(16) __half g_h16C[3ll * NN * 128];  // conv2 gemm out
__device__ float  g_feats[GG * F6];
__device__ float  g_mlp1[GG * 256];
__device__ float  g_mlp2[GG * 128];
__device__ int    g_cntg[GG];

// ---------------- CSR + CSC build ----------------
__global__ void hist_e(const int* __restrict__ row, const int* __restrict__ col) {
    int e = blockIdx.x * blockDim.x + threadIdx.x;
    if (e >= EE) return;
    atomicAdd(&g_cntR[row[e]], 1);
    atomicAdd(&g_cntC[col[e]], 1);
}

__device__ __forceinline__ void block_incl_scan(int* sh, int tid) {
#pragma unroll
    for (int off = 1; off < 1024; off <<= 1) {
        int t = (tid >= off) ? sh[tid - off] : 0;
        __syncthreads();
        sh[tid] += t;
        __syncthreads();
    }
}

__global__ void scan_local(const int* __restrict__ cntA, int* __restrict__ inclA,
                           int* __restrict__ bsumA, const int* __restrict__ cntB,
                           int* __restrict__ inclB, int* __restrict__ bsumB) {
    __shared__ int sh[1024];
    int tid = threadIdx.x;
    int i = blockIdx.x * 1024 + tid;
    sh[tid] = (i < NN) ? cntA[i] : 0;
    __syncthreads();
    block_incl_scan(sh, tid);
    if (i < NN) inclA[i] = sh[tid];
    if (tid == 1023) bsumA[blockIdx.x] = sh[1023];
    __syncthreads();
    sh[tid] = (i < NN) ? cntB[i] : 0;
    __syncthreads();
    block_incl_scan(sh, tid);
    if (i < NN) inclB[i] = sh[tid];
    if (tid == 1023) bsumB[blockIdx.x] = sh[1023];
}

__global__ void scan_mid_k() {
    __shared__ int sh[128];
    __shared__ int orig[128];
    int tid = threadIdx.x;
#pragma unroll
    for (int pass = 0; pass < 2; pass++) {
        int* bsum = pass ? g_bsumC : g_bsumR;
        int v = (tid < NB) ? bsum[tid] : 0;
        sh[tid] = v;
        orig[tid] = v;
        __syncthreads();
#pragma unroll
        for (int off = 1; off < 128; off <<= 1) {
            int t = (tid >= off) ? sh[tid - off] : 0;
            __syncthreads();
            sh[tid] += t;
            __syncthreads();
        }
        if (tid < NB) bsum[tid] = sh[tid] - orig[tid];
        __syncthreads();
    }
}

__global__ void scan_final(const int* __restrict__ cntA, const int* __restrict__ inclA,
                           const int* __restrict__ bsumA, int* __restrict__ startA,
                           int* __restrict__ curA, const int* __restrict__ cntB,
                           const int* __restrict__ inclB, const int* __restrict__ bsumB,
                           int* __restrict__ startB, int* __restrict__ curB) {
    int i = blockIdx.x * 1024 + threadIdx.x;
    if (i >= NN) return;
    int blk = blockIdx.x;
    int eA = bsumA[blk] + inclA[i] - cntA[i];
    startA[i] = eA;
    curA[i] = eA;
    int eB = bsumB[blk] + inclB[i] - cntB[i];
    startB[i] = eB;
    curB[i] = eB;
    if (i == 0) { startA[NN] = EE; startB[NN] = EE; }
}

__global__ void scatter_e(const int* __restrict__ row, const int* __restrict__ col) {
    int e = blockIdx.x * blockDim.x + threadIdx.x;
    if (e >= EE) return;
    int r = row[e], c = col[e];
    int p1 = atomicAdd(&g_curR[r], 1);
    g_col[p1] = c;
    int p2 = atomicAdd(&g_curC[c], 1);
    g_crow[p2] = r;
    g_c2c[p1] = p2;  // CSR slot -> CSC slot
}

// ---------------- per-node attention scores (all 3 blocks) ----------------
__global__ void s12_k(const float* __restrict__ x, const float* __restrict__ att) {
    int t = blockIdx.x * blockDim.x + threadIdx.x;
    int u = t >> 5, lane = t & 31;
    if (u >= NN) return;
    float4 xv = *(const float4*)&x[u * 128 + lane * 4];
#pragma unroll
    for (int b = 0; b < 3; b++) {
        float4 a1 = *(const float4*)&att[b * 256 + lane * 4];
        float4 a2 = *(const float4*)&att[b * 256 + 128 + lane * 4];
        float d1 = xv.x * a1.x + xv.y * a1.y + xv.z * a1.z + xv.w * a1.w;
        float d2 = xv.x * a2.x + xv.y * a2.y + xv.z * a2.z + xv.w * a2.w;
#pragma unroll
        for (int o = 16; o > 0; o >>= 1) {
            d1 += __shfl_xor_sync(0xffffffffu, d1, o);
            d2 += __shfl_xor_sync(0xffffffffu, d2, o);
        }
        if (lane == 0) {
            g_s1[b * NN + u] = d1;
            g_s2[b * NN + u] = d2;
        }
    }
}

__device__ __forceinline__ float lrelu(float w) { return w >= 0.f ? w : NEG * w; }

// ---------------- exact segment sparsemax, all 3 blocks; writes p in CSC order ----------------
__global__ void sparsemax_all_k() {
    __shared__ int   shc[8][SCAP];   // dest ids (CSR order)
    __shared__ int   shm[8][SCAP];   // CSC slot per edge
    __shared__ float shz[8][SCAP];
    int lane = threadIdx.x & 31, wl = threadIdx.x >> 5;
    int u = blockIdx.x * 8 + wl;
    if (u >= NN) return;
    int st = g_startR[u], en = g_startR[u + 1];
    int d = en - st;
    if (d == 0) return;
    int* shci = shc[wl];
    int* shmi = shm[wl];
    float* shzi = shz[wl];
    for (int i = lane; i < d; i += 32) {
        if (i < SCAP) {
            shci[i] = g_col[st + i];
            shmi[i] = g_c2c[st + i];
        }
    }
    __syncwarp();
#pragma unroll
    for (int b = 0; b < 3; b++) {
        float su = g_s1[b * NN + u];
        const float* s2b = &g_s2[b * NN];
        for (int i = lane; i < d; i += 32) {
            if (i < SCAP) shzi[i] = lrelu(su + s2b[shci[i]]);
        }
        __syncwarp();
        float kloc = 0.f, sloc = 0.f;
        for (int i = lane; i < d; i += 32) {
            float zi = (i < SCAP) ? shzi[i] : lrelu(su + s2b[g_col[st + i]]);
            float rank = 1.f, S = zi;
            for (int j = 0; j < d; j++) {
                float zj = (j < SCAP) ? shzi[j] : lrelu(su + s2b[g_col[st + j]]);
                if (zj > zi || (zj == zi && j < i)) { rank += 1.f; S += zj; }
            }
            if (1.f + rank * zi > S) { kloc += 1.f; sloc += zi; }
        }
#pragma unroll
        for (int o = 16; o > 0; o >>= 1) {
            kloc += __shfl_xor_sync(0xffffffffu, kloc, o);
            sloc += __shfl_xor_sync(0xffffffffu, sloc, o);
        }
        float tau = (sloc - 1.f) / kloc;  // k >= 1 always
        for (int i = lane; i < d; i += 32) {
            float zi = (i < SCAP) ? shzi[i] : lrelu(su + s2b[g_col[st + i]]);
            int cs = (i < SCAP) ? shmi[i] : g_c2c[st + i];
            g_pc[(long long)b * EE + cs] = fmaxf(zi - tau, 0.f);  // scatter to CSC order
        }
        __syncwarp();
    }
}

// ---------------- dinv for all 3 blocks (coalesced CSC p reads) ----------------
__global__ void dinv_all_k() {
    int t = blockIdx.x * blockDim.x + threadIdx.x;
    int v = t >> 5, lane = t & 31;
    if (v >= NN) return;
    int st = g_startC[v], d = g_startC[v + 1] - st;
    float s0 = 0.f, s1 = 0.f, s2 = 0.f;
    for (int i = lane; i < d; i += 32) {
        s0 += g_pc[st + i];
        s1 += g_pc[EE + st + i];
        s2 += g_pc[2 * EE + st + i];
    }
#pragma unroll
    for (int o = 16; o > 0; o >>= 1) {
        s0 += __shfl_xor_sync(0xffffffffu, s0, o);
        s1 += __shfl_xor_sync(0xffffffffu, s1, o);
        s2 += __shfl_xor_sync(0xffffffffu, s2, o);
    }
    if (lane == 0) {
        g_dinv[v] = rsqrtf(s0 + 1.0f);
        g_dinv[NN + v] = rsqrtf(s1 + 1.0f);
        g_dinv[2 * NN + v] = rsqrtf(s2 + 1.0f);
    }
}

// ---------------- compact live edges per (block, dest): (u, dinv[u]*p) pairs ----------------
__global__ void ecoef_compact_k() {
    int t = blockIdx.x * blockDim.x + threadIdx.x;
    int v = t >> 5, lane = t & 31;
    if (v >= NN) return;
    int st = g_startC[v], d = g_startC[v + 1] - st;
#pragma unroll
    for (int b = 0; b < 3; b++) {
        int cnt = 0;
        for (int j0 = 0; j0 < d; j0 += 32) {
            int i = j0 + lane;
            int u = 0;
            float e = 0.f;
            bool live = false;
            if (i < d) {
                u = g_crow[st + i];
                float pv = g_pc[(long long)b * EE + st + i];  // coalesced
                if (pv > 0.f) {
                    e = g_dinv[b * NN + u] * pv;
                    live = true;
                }
            }
            unsigned mask = __ballot_sync(0xffffffffu, live);
            int pos = cnt + __popc(mask & ((1u << lane) - 1u));
            if (live)
                g_ecc[(long long)b * EE + st + pos] = make_float2(__int_as_float(u), e);
            cnt += __popc(mask);
        }
        if (lane == 0) g_lcnt[b * NN + v] = cnt;
    }
}

// ---------------- fp16 HMMA GEMM, batched over blockIdx.y ----------------
__global__ __launch_bounds__(512) void gemm_h16_k(const float* __restrict__ Af,
                                                  const __half* __restrict__ Ah,
                                                  long long astride,
                                                  const float* __restrict__ Wbase,
                                                  __half* __restrict__ Obase,
                                                  long long ostride) {
    extern __shared__ char smem[];
    __half* Ws = (__half*)smem;                        // [128][LDH]
    __half* As = (__half*)(smem + WS_BYTES);           // [128][LDH]
    float* Est = (float*)(smem + WS_BYTES + AS_BYTES); // [128][128]
    int tid = threadIdx.x;
    int m0 = blockIdx.x * 128;
    int by = blockIdx.y;
    const float* W = Wbase + (long long)by * 16384;
    __half* O = Obase + (long long)by * ostride;
    const __half* Ahp = Ah ? (Ah + (long long)by * astride) : (const __half*)0;

#pragma unroll
    for (int l = 0; l < 8; l++) {
        int idx = tid + l * 512;
        int r = idx >> 5, k4 = idx & 31;
        int gm = m0 + r;
        __half2 p0 = __floats2half2_rn(0.f, 0.f), p1 = p0;
        if (gm < NN) {
            if (Ahp) {
                const __half2* ap = (const __half2*)&Ahp[(long long)gm * 128 + k4 * 4];
                p0 = ap[0];
                p1 = ap[1];
            } else {
                float4 v = *(const float4*)&Af[(long long)gm * 128 + k4 * 4];
                p0 = __floats2half2_rn(v.x, v.y);
                p1 = __floats2half2_rn(v.z, v.w);
            }
        }
        __half2* dst = (__half2*)&As[r * LDH + k4 * 4];
        dst[0] = p0;
        dst[1] = p1;
    }
#pragma unroll
    for (int l = 0; l < 8; l++) {
        int idx = tid + l * 512;
        int r = idx >> 5, c4 = idx & 31;
        float4 v = *(const float4*)&W[r * 128 + c4 * 4];
        __half2* dst = (__half2*)&Ws[r * LDH + c4 * 4];
        dst[0] = __floats2half2_rn(v.x, v.y);
        dst[1] = __floats2half2_rn(v.z, v.w);
    }
    __syncthreads();

    int warp = tid >> 5;
    int mi = warp & 7;
    int nh = (warp >> 3) * 64;
    int gm = m0 + mi * 16;

    wmma::fragment<wmma::accumulator, 16, 16, 16, float> acc[4];
#pragma unroll
    for (int t = 0; t < 4; t++) wmma::fill_fragment(acc[t], 0.f);
#pragma unroll
    for (int k = 0; k < 128; k += 16) {
        wmma::fragment<wmma::matrix_a, 16, 16, 16, __half, wmma::row_major> af;
        wmma::load_matrix_sync(af, As + mi * 16 * LDH + k, LDH);
#pragma unroll
        for (int t = 0; t < 4; t++) {
            wmma::fragment<wmma::matrix_b, 16, 16, 16, __half, wmma::row_major> bf;
            wmma::load_matrix_sync(bf, Ws + k * LDH + nh + t * 16, LDH);
            wmma::mma_sync(acc[t], af, bf, acc[t]);
        }
    }

#pragma unroll
    for (int t = 0; t < 4; t++)
        wmma::store_matrix_sync(Est + mi * 16 * 128 + nh + t * 16, acc[t], 128,
                                wmma::mem_row_major);
    __syncthreads();
#pragma unroll
    for (int l = 0; l < 8; l++) {
        int idx = tid + l * 512;
        int r = idx >> 5, c4 = idx & 31;
        int gr = m0 + r;
        if (gr < NN) {
            float4 vv = *(const float4*)&Est[r * 128 + c4 * 4];
            __half2* op = (__half2*)&O[(long long)gr * 128 + c4 * 4];
            op[0] = __floats2half2_rn(vv.x, vv.y);
            op[1] = __floats2half2_rn(vv.z, vv.w);
        }
    }
}

// ---------------- GCN aggregation, batched over blockIdx.y ----------------
__global__ void gather_conv_k(const __half* __restrict__ hbase,
                              const float* __restrict__ biasbase,
                              __half* __restrict__ outbase) {
    int b = blockIdx.y;
    const __half* h = hbase + (long long)b * NNL * 128;
    __half* out = outbase + (long long)b * NNL * 128;
    const float* bias = biasbase + b * 128;
    const float2* ecc = g_ecc + (long long)b * EE;
    const int* lcnt = g_lcnt + b * NN;
    const float* dinv = g_dinv + b * NN;

    int t = blockIdx.x * blockDim.x + threadIdx.x;
    int v = t >> 5, lane = t & 31;
    if (v >= NN) return;
    int st = g_startC[v];
    int cnt = lcnt[v];
    float4 acc = make_float4(0.f, 0.f, 0.f, 0.f);
    for (int j0 = 0; j0 < cnt; j0 += 32) {
        int i = j0 + lane;
        float2 pr = make_float2(0.f, 0.f);
        if (i < cnt) pr = ecc[st + i];
        int lim = min(32, cnt - j0);
        for (int j = 0; j < lim; j++) {
            float cj = __shfl_sync(0xffffffffu, pr.y, j);
            int uj = __float_as_int(__shfl_sync(0xffffffffu, pr.x, j));
            const __half2* hp = (const __half2*)&h[(long long)uj * 128 + lane * 4];
            float2 lo = __half22float2(hp[0]);
            float2 hi = __half22float2(hp[1]);
            acc.x += cj * lo.x; acc.y += cj * lo.y;
            acc.z += cj * hi.x; acc.w += cj * hi.y;
        }
    }
    float dv = dinv[v];
    const __half2* sp = (const __half2*)&h[(long long)v * 128 + lane * 4];
    float2 slo = __half22float2(sp[0]);
    float2 shi = __half22float2(sp[1]);
    float4 bv = *(const float4*)&bias[lane * 4];
    float ox = fmaxf(bv.x + dv * (acc.x + dv * slo.x), 0.f);
    float oy = fmaxf(bv.y + dv * (acc.y + dv * slo.y), 0.f);
    float oz = fmaxf(bv.z + dv * (acc.z + dv * shi.x), 0.f);
    float ow = fmaxf(bv.w + dv * (acc.w + dv * shi.y), 0.f);
    __half2* op = (__half2*)&out[(long long)v * 128 + lane * 4];
    op[0] = __floats2half2_rn(ox, oy);
    op[1] = __floats2half2_rn(oz, ow);
}

// ---------------- pooling, batched over blockIdx.y ----------------
__global__ void hist_batch_k(const int* __restrict__ batch) {
    int i = blockIdx.x * blockDim.x + threadIdx.x;
    if (i < NN) atomicAdd(&g_cntg[batch[i]], 1);
}

__global__ void pool_k(const __half* __restrict__ zbase, const int* __restrict__ batch) {
    int b = blockIdx.y;
    const __half* z = zbase + (long long)b * NNL * 128;
    int boff = b * 256;
    int f = threadIdx.x;  // 128 threads = one feature each
    int n0 = blockIdx.x * 256;
    if (n0 >= NN) return;
    int nend = min(n0 + 256, NN);
    int cur = batch[n0];
    float ls = 0.f, lm = 0.f;
    for (int n = n0; n < nend; n++) {
        int g = batch[n];
        if (g != cur) {
            atomicAdd(&g_feats[cur * F6 + boff + f], ls);
            atomicMax((int*)&g_feats[cur * F6 + boff + 128 + f], __float_as_int(lm));
            ls = 0.f; lm = 0.f; cur = g;
        }
        float v = __half2float(z[(long long)n * 128 + f]);  // already relu'd (>= 0)
        ls += v;
        lm = fmaxf(lm, v);
    }
    atomicAdd(&g_feats[cur * F6 + boff + f], ls);
    atomicMax((int*)&g_feats[cur * F6 + boff + 128 + f], __float_as_int(lm));
}

// ---------------- tiny MLP head (mean finalize folded into mlp1) ----------------
__global__ void mlp1_k(const float* __restrict__ w, const float* __restrict__ bias) {
    __shared__ float sh[F6];
    int g = blockIdx.x, j = threadIdx.x;  // 256 threads
    float inv = 1.0f / (float)max(g_cntg[g], 1);
    for (int i = j; i < F6; i += 256) {
        float v = g_feats[g * F6 + i];
        if ((i & 255) < 128) v *= inv;  // mean slots: divide by node count
        sh[i] = v;
    }
    __syncthreads();
    float acc = bias[j];
#pragma unroll 8
    for (int i = 0; i < F6; i++) acc += sh[i] * w[i * 256 + j];
    g_mlp1[g * 256 + j] = fmaxf(acc, 0.f);
}

__global__ void mlp2_k(const float* __restrict__ w, const float* __restrict__ bias) {
    __shared__ float sh[256];
    int g = blockIdx.x, j = threadIdx.x;  // 128 threads
    for (int i = j; i < 256; i += 128) sh[i] = g_mlp1[g * 256 + i];
    __syncthreads();
    float acc = bias[j];
#pragma unroll 8
    for (int i = 0; i < 256; i++) acc += sh[i] * w[i * 128 + j];
    g_mlp2[g * 128 + j] = fmaxf(acc, 0.f);
}

__global__ void mlp3_k(const float* __restrict__ w, const float* __restrict__ bias,
                       float* __restrict__ out) {
    int g = blockIdx.x, lane = threadIdx.x;  // 32 threads
    __shared__ float sh[128];
    for (int i = lane; i < 128; i += 32) sh[i] = g_mlp2[g * 128 + i];
    __syncwarp();
    float acc[NCLS];
#pragma unroll
    for (int c = 0; c < NCLS; c++) acc[c] = 0.f;
    for (int i = lane; i < 128; i += 32) {
        float v = sh[i];
#pragma unroll
        for (int c = 0; c < NCLS; c++) acc[c] += v * w[i * NCLS + c];
    }
#pragma unroll
    for (int c = 0; c < NCLS; c++)
#pragma unroll
        for (int o = 16; o > 0; o >>= 1) acc[c] += __shfl_xor_sync(0xffffffffu, acc[c], o);
    if (lane == 0) {
        float vals[NCLS], m = -1e30f;
        for (int c = 0; c < NCLS; c++) { vals[c] = acc[c] + bias[c]; m = fmaxf(m, vals[c]); }
        float s = 0.f;
        for (int c = 0; c < NCLS; c++) s += expf(vals[c] - m);
        float lse = logf(s);
        for (int c = 0; c < NCLS; c++) out[g * NCLS + c] = vals[c] - m - lse;
    }
}

// ---------------- host launch ----------------
extern "C" void kernel_launch(void* const* d_in, const int* in_sizes, int n_in,
                              void* d_out, int out_size) {
    const float* x = (const float*)d_in[0];
    const int* ei = (const int*)d_in[1];
    // d_in[2] = edge_attr: unused by the reference
    const int* batch = (const int*)d_in[3];
    int pi = (n_in >= 16) ? 5 : 4;
    const float* att  = (const float*)d_in[pi + 0];
    const float* W1   = (const float*)d_in[pi + 1];
    const float* b1   = (const float*)d_in[pi + 2];
    const float* W2   = (const float*)d_in[pi + 3];
    const float* b2   = (const float*)d_in[pi + 4];
    const float* fc1w = (const float*)d_in[pi + 5];
    const float* fc1b = (const float*)d_in[pi + 6];
    const float* fc2w = (const float*)d_in[pi + 7];
    const float* fc2b = (const float*)d_in[pi + 8];
    const float* fc3w = (const float*)d_in[pi + 9];
    const float* fc3b = (const float*)d_in[pi + 10];
    float* out = (float*)d_out;

    float* feats;
    __half *h16A, *h16B, *h16C;
    int *cntR, *cntC, *startR, *startC, *curR, *curC;
    int *inclR, *inclC, *bsumR, *bsumC, *cntg;
    cudaGetSymbolAddress((void**)&h16A, g_h16A);
    cudaGetSymbolAddress((void**)&h16B, g_h16B);
    cudaGetSymbolAddress((void**)&h16C, g_h16C);
    cudaGetSymbolAddress((void**)&feats, g_feats);
    cudaGetSymbolAddress((void**)&cntR, g_cntR);
    cudaGetSymbolAddress((void**)&cntC, g_cntC);
    cudaGetSymbolAddress((void**)&startR, g_startR);
    cudaGetSymbolAddress((void**)&startC, g_startC);
    cudaGetSymbolAddress((void**)&curR, g_curR);
    cudaGetSymbolAddress((void**)&curC, g_curC);
    cudaGetSymbolAddress((void**)&inclR, g_inclR);
    cudaGetSymbolAddress((void**)&inclC, g_inclC);
    cudaGetSymbolAddress((void**)&bsumR, g_bsumR);
    cudaGetSymbolAddress((void**)&bsumC, g_bsumC);
    cudaGetSymbolAddress((void**)&cntg, g_cntg);

    cudaFuncSetAttribute(gemm_h16_k, cudaFuncAttributeMaxDynamicSharedMemorySize,
                         GEMM_SMEM_BYTES);

    // side streams + events for capture-compatible fork/join
    static cudaStream_t sA = 0, sB = 0;
    static cudaEvent_t evRoot = 0, evA = 0, evB = 0;
    if (!sA) {
        cudaStreamCreateWithFlags(&sA, cudaStreamNonBlocking);
        cudaStreamCreateWithFlags(&sB, cudaStreamNonBlocking);
        cudaEventCreateWithFlags(&evRoot, cudaEventDisableTiming);
        cudaEventCreateWithFlags(&evA, cudaEventDisableTiming);
        cudaEventCreateWithFlags(&evB, cudaEventDisableTiming);
    }

    const int* row = ei;
    const int* col = ei + EE;

    cudaMemsetAsync(cntR, 0, NN * sizeof(int));
    cudaMemsetAsync(cntC, 0, NN * sizeof(int));
    cudaMemsetAsync(cntg, 0, GG * sizeof(int));
    cudaMemsetAsync(feats, 0, GG * F6 * sizeof(float));
    cudaEventRecord(evRoot, 0);

    // branch A: batched conv1 GEMM — depends only on x, W1
    cudaStreamWaitEvent(sA, evRoot, 0);
    gemm_h16_k<<<dim3(cdiv(NN, 128), 3), 512, GEMM_SMEM_BYTES, sA>>>(
        x, (const __half*)0, 0ll, W1, h16A, NNL * 128);
    cudaEventRecord(evA, sA);

    // branch B: attention scores + per-graph counts
    cudaStreamWaitEvent(sB, evRoot, 0);
    s12_k<<<cdiv(NN * 32, 256), 256, 0, sB>>>(x, att);
    hist_batch_k<<<cdiv(NN, 256), 256, 0, sB>>>(batch);
    cudaEventRecord(evB, sB);

    // main branch: CSR/CSC build
    hist_e<<<cdiv(EE, 256), 256>>>(row, col);
    scan_local<<<NB, 1024>>>(cntR, inclR, bsumR, cntC, inclC, bsumC);
    scan_mid_k<<<1, 128>>>();
    scan_final<<<NB, 1024>>>(cntR, inclR, bsumR, startR, curR,
                             cntC, inclC, bsumC, startC, curC);
    scatter_e<<<cdiv(EE, 256), 256>>>(row, col);

    // join B: sparsemax needs s1/s2 + CSR
    cudaStreamWaitEvent(0, evB, 0);
    sparsemax_all_k<<<cdiv(NN, 8), 256>>>();
    dinv_all_k<<<cdiv(NN * 32, 256), 256>>>();
    ecoef_compact_k<<<cdiv(NN * 32, 256), 256>>>();

    // join A: gathers need the conv1 GEMM output
    cudaStreamWaitEvent(0, evA, 0);
    gather_conv_k<<<dim3(cdiv(NN * 32, 256), 3), 256>>>(h16A, b1, h16B);
    gemm_h16_k<<<dim3(cdiv(NN, 128), 3), 512, GEMM_SMEM_BYTES>>>(
        (const float*)0, h16B, NNL * 128, W2, h16C, NNL * 128);
    gather_conv_k<<<dim3(cdiv(NN * 32, 256), 3), 256>>>(h16C, b2, h16A);
    pool_k<<<dim3(cdiv(NN, 256), 3), 128>>>(h16A, batch);

    mlp1_k<<<GG, 256>>>(fc1w, fc1b);
    mlp2_k<<<GG, 128>>>(fc2w, fc2b);
    mlp3_k<<<GG, 32>>>(fc3w, fc3b, out);

    (void)in_sizes;
    (void)out_size;
}

// round 17
// speedup vs baseline: 1.1029x; 1.0058x over previous
#include <cuda_runtime.h>
#include <cuda_fp16.h>
#include <mma.h>
#include <math.h>

using namespace nvcuda;

#define NN 100000
#define EE 1600000
#define GG 256
#define NCLS 10
#define F6 768
#define SCAP 192
#define NEG 0.2f
#define NB 98  // cdiv(NN, 1024)
#define NNL ((long long)NN)

#define LDH 136  // half-element leading dim for A/W smem tiles
#define WS_BYTES (128 * LDH * 2)
#define AS_BYTES (128 * LDH * 2)
#define EST_BYTES (128 * 128 * 4)  // block-wide fp32 epilogue staging
#define GEMM_SMEM_BYTES (WS_BYTES + AS_BYTES + EST_BYTES)

static inline int cdiv(int a, int b) { return (a + b - 1) / b; }

// ---------------- device scratch (no allocations allowed) ----------------
__device__ int    g_cntR[NN];
__device__ int    g_cntC[NN];
__device__ int    g_startR[NN + 1];
__device__ int    g_startC[NN + 1];
__device__ int    g_curR[NN];
__device__ int    g_curC[NN];
__device__ int    g_inclR[NN];
__device__ int    g_inclC[NN];
__device__ int    g_bsumR[NB];
__device__ int    g_bsumC[NB];
__device__ int    g_col[EE];        // CSR (by source): dest of each slot
__device__ int    g_crow[EE];       // CSC (by dest): source of each slot
__device__ int    g_c2c[EE];        // CSR slot -> CSC slot
__device__ float  g_pc[3 * EE];     // sparsemax weights, CSC order, per block
__device__ __align__(16) float2 g_ecc[3ll * EE];  // compacted live edges (u, ec)
__device__ int    g_lcnt[3 * NN];   // live-edge count per (block, dest)
__device__ float  g_s1[3 * NN];
__device__ float  g_s2[3 * NN];
__device__ float  g_dinv[3 * NN];
__device__ __align__(16) __half g_h16A[3ll * NN * 128];  // conv1 gemm out / conv2 gather out
__device__ __align__(16) __half g_h16B[3ll * NN * 128];  // conv1 gather out (gemm2 in)
__device__ __align__(16) __half g_h16C[3ll * NN * 128];  // conv2 gemm out
__device__ float  g_feats[GG * F6];
__device__ float  g_mlp1[GG * 256];
__device__ float  g_mlp2[GG * 128];
__device__ int    g_cntg[GG];

// ---------------- CSR + CSC build ----------------
__global__ void hist_e(const int* __restrict__ row, const int* __restrict__ col) {
    int e = blockIdx.x * blockDim.x + threadIdx.x;
    if (e >= EE) return;
    atomicAdd(&g_cntR[row[e]], 1);
    atomicAdd(&g_cntC[col[e]], 1);
}

__device__ __forceinline__ void block_incl_scan(int* sh, int tid) {
#pragma unroll
    for (int off = 1; off < 1024; off <<= 1) {
        int t = (tid >= off) ? sh[tid - off] : 0;
        __syncthreads();
        sh[tid] += t;
        __syncthreads();
    }
}

__global__ void scan_local(const int* __restrict__ cntA, int* __restrict__ inclA,
                           int* __restrict__ bsumA, const int* __restrict__ cntB,
                           int* __restrict__ inclB, int* __restrict__ bsumB) {
    __shared__ int sh[1024];
    int tid = threadIdx.x;
    int i = blockIdx.x * 1024 + tid;
    sh[tid] = (i < NN) ? cntA[i] : 0;
    __syncthreads();
    block_incl_scan(sh, tid);
    if (i < NN) inclA[i] = sh[tid];
    if (tid == 1023) bsumA[blockIdx.x] = sh[1023];
    __syncthreads();
    sh[tid] = (i < NN) ? cntB[i] : 0;
    __syncthreads();
    block_incl_scan(sh, tid);
    if (i < NN) inclB[i] = sh[tid];
    if (tid == 1023) bsumB[blockIdx.x] = sh[1023];
}

__global__ void scan_mid_k() {
    __shared__ int sh[128];
    __shared__ int orig[128];
    int tid = threadIdx.x;
#pragma unroll
    for (int pass = 0; pass < 2; pass++) {
        int* bsum = pass ? g_bsumC : g_bsumR;
        int v = (tid < NB) ? bsum[tid] : 0;
        sh[tid] = v;
        orig[tid] = v;
        __syncthreads();
#pragma unroll
        for (int off = 1; off < 128; off <<= 1) {
            int t = (tid >= off) ? sh[tid - off] : 0;
            __syncthreads();
            sh[tid] += t;
            __syncthreads();
        }
        if (tid < NB) bsum[tid] = sh[tid] - orig[tid];
        __syncthreads();
    }
}

__global__ void scan_final(const int* __restrict__ cntA, const int* __restrict__ inclA,
                           const int* __restrict__ bsumA, int* __restrict__ startA,
                           int* __restrict__ curA, const int* __restrict__ cntB,
                           const int* __restrict__ inclB, const int* __restrict__ bsumB,
                           int* __restrict__ startB, int* __restrict__ curB) {
    int i = blockIdx.x * 1024 + threadIdx.x;
    if (i >= NN) return;
    int blk = blockIdx.x;
    int eA = bsumA[blk] + inclA[i] - cntA[i];
    startA[i] = eA;
    curA[i] = eA;
    int eB = bsumB[blk] + inclB[i] - cntB[i];
    startB[i] = eB;
    curB[i] = eB;
    if (i == 0) { startA[NN] = EE; startB[NN] = EE; }
}

__global__ void scatter_e(const int* __restrict__ row, const int* __restrict__ col) {
    int e = blockIdx.x * blockDim.x + threadIdx.x;
    if (e >= EE) return;
    int r = row[e], c = col[e];
    int p1 = atomicAdd(&g_curR[r], 1);
    g_col[p1] = c;
    int p2 = atomicAdd(&g_curC[c], 1);
    g_crow[p2] = r;
    g_c2c[p1] = p2;  // CSR slot -> CSC slot
}

// ---------------- per-node attention scores (all 3 blocks) ----------------
__global__ void s12_k(const float* __restrict__ x, const float* __restrict__ att) {
    int t = blockIdx.x * blockDim.x + threadIdx.x;
    int u = t >> 5, lane = t & 31;
    if (u >= NN) return;
    float4 xv = *(const float4*)&x[u * 128 + lane * 4];
#pragma unroll
    for (int b = 0; b < 3; b++) {
        float4 a1 = *(const float4*)&att[b * 256 + lane * 4];
        float4 a2 = *(const float4*)&att[b * 256 + 128 + lane * 4];
        float d1 = xv.x * a1.x + xv.y * a1.y + xv.z * a1.z + xv.w * a1.w;
        float d2 = xv.x * a2.x + xv.y * a2.y + xv.z * a2.z + xv.w * a2.w;
#pragma unroll
        for (int o = 16; o > 0; o >>= 1) {
            d1 += __shfl_xor_sync(0xffffffffu, d1, o);
            d2 += __shfl_xor_sync(0xffffffffu, d2, o);
        }
        if (lane == 0) {
            g_s1[b * NN + u] = d1;
            g_s2[b * NN + u] = d2;
        }
    }
}

__device__ __forceinline__ float lrelu(float w) { return w >= 0.f ? w : NEG * w; }

// ---------------- exact segment sparsemax, all 3 blocks; writes p in CSC order ----------------
__global__ void sparsemax_all_k() {
    __shared__ int   shc[8][SCAP];   // dest ids (CSR order)
    __shared__ int   shm[8][SCAP];   // CSC slot per edge
    __shared__ float shz[8][SCAP];
    int lane = threadIdx.x & 31, wl = threadIdx.x >> 5;
    int u = blockIdx.x * 8 + wl;
    if (u >= NN) return;
    int st = g_startR[u], en = g_startR[u + 1];
    int d = en - st;
    if (d == 0) return;
    int* shci = shc[wl];
    int* shmi = shm[wl];
    float* shzi = shz[wl];
    for (int i = lane; i < d; i += 32) {
        if (i < SCAP) {
            shci[i] = g_col[st + i];
            shmi[i] = g_c2c[st + i];
        }
    }
    __syncwarp();
#pragma unroll
    for (int b = 0; b < 3; b++) {
        float su = g_s1[b * NN + u];
        const float* s2b = &g_s2[b * NN];
        for (int i = lane; i < d; i += 32) {
            if (i < SCAP) shzi[i] = lrelu(su + s2b[shci[i]]);
        }
        __syncwarp();
        float kloc = 0.f, sloc = 0.f;
        for (int i = lane; i < d; i += 32) {
            float zi = (i < SCAP) ? shzi[i] : lrelu(su + s2b[g_col[st + i]]);
            float rank = 1.f, S = zi;
            for (int j = 0; j < d; j++) {
                float zj = (j < SCAP) ? shzi[j] : lrelu(su + s2b[g_col[st + j]]);
                if (zj > zi || (zj == zi && j < i)) { rank += 1.f; S += zj; }
            }
            if (1.f + rank * zi > S) { kloc += 1.f; sloc += zi; }
        }
#pragma unroll
        for (int o = 16; o > 0; o >>= 1) {
            kloc += __shfl_xor_sync(0xffffffffu, kloc, o);
            sloc += __shfl_xor_sync(0xffffffffu, sloc, o);
        }
        float tau = (sloc - 1.f) / kloc;  // k >= 1 always
        for (int i = lane; i < d; i += 32) {
            float zi = (i < SCAP) ? shzi[i] : lrelu(su + s2b[g_col[st + i]]);
            int cs = (i < SCAP) ? shmi[i] : g_c2c[st + i];
            g_pc[(long long)b * EE + cs] = fmaxf(zi - tau, 0.f);  // scatter to CSC order
        }
        __syncwarp();
    }
}

// ---------------- dinv for all 3 blocks (coalesced CSC p reads) ----------------
__global__ void dinv_all_k() {
    int t = blockIdx.x * blockDim.x + threadIdx.x;
    int v = t >> 5, lane = t & 31;
    if (v >= NN) return;
    int st = g_startC[v], d = g_startC[v + 1] - st;
    float s0 = 0.f, s1 = 0.f, s2 = 0.f;
    for (int i = lane; i < d; i += 32) {
        s0 += g_pc[st + i];
        s1 += g_pc[EE + st + i];
        s2 += g_pc[2 * EE + st + i];
    }
#pragma unroll
    for (int o = 16; o > 0; o >>= 1) {
        s0 += __shfl_xor_sync(0xffffffffu, s0, o);
        s1 += __shfl_xor_sync(0xffffffffu, s1, o);
        s2 += __shfl_xor_sync(0xffffffffu, s2, o);
    }
    if (lane == 0) {
        g_dinv[v] = rsqrtf(s0 + 1.0f);
        g_dinv[NN + v] = rsqrtf(s1 + 1.0f);
        g_dinv[2 * NN + v] = rsqrtf(s2 + 1.0f);
    }
}

// ---------------- compact live edges per (block, dest): (u, dinv[u]*p) pairs ----------------
__global__ void ecoef_compact_k() {
    int t = blockIdx.x * blockDim.x + threadIdx.x;
    int v = t >> 5, lane = t & 31;
    if (v >= NN) return;
    int st = g_startC[v], d = g_startC[v + 1] - st;
#pragma unroll
    for (int b = 0; b < 3; b++) {
        int cnt = 0;
        for (int j0 = 0; j0 < d; j0 += 32) {
            int i = j0 + lane;
            int u = 0;
            float e = 0.f;
            bool live = false;
            if (i < d) {
                u = g_crow[st + i];
                float pv = g_pc[(long long)b * EE + st + i];  // coalesced
                if (pv > 0.f) {
                    e = g_dinv[b * NN + u] * pv;
                    live = true;
                }
            }
            unsigned mask = __ballot_sync(0xffffffffu, live);
            int pos = cnt + __popc(mask & ((1u << lane) - 1u));
            if (live)
                g_ecc[(long long)b * EE + st + pos] = make_float2(__int_as_float(u), e);
            cnt += __popc(mask);
        }
        if (lane == 0) g_lcnt[b * NN + v] = cnt;
    }
}

// ---------------- fp16 HMMA GEMM, batched over blockIdx.y ----------------
// 512 threads, M=128 x N=128 CTA tile, 32x32 warp tile (4x4 warp grid):
// per k-step 2 A-frags + 2 B-frags feed 4 mmas (1.0 frag-loads/mma).
__global__ __launch_bounds__(512) void gemm_h16_k(const float* __restrict__ Af,
                                                  const __half* __restrict__ Ah,
                                                  long long astride,
                                                  const float* __restrict__ Wbase,
                                                  __half* __restrict__ Obase,
                                                  long long ostride) {
    extern __shared__ char smem[];
    __half* Ws = (__half*)smem;                        // [128][LDH]
    __half* As = (__half*)(smem + WS_BYTES);           // [128][LDH]
    float* Est = (float*)(smem + WS_BYTES + AS_BYTES); // [128][128]
    int tid = threadIdx.x;
    int m0 = blockIdx.x * 128;
    int by = blockIdx.y;
    const float* W = Wbase + (long long)by * 16384;
    __half* O = Obase + (long long)by * ostride;
    const __half* Ahp = Ah ? (Ah + (long long)by * astride) : (const __half*)0;

#pragma unroll
    for (int l = 0; l < 8; l++) {
        int idx = tid + l * 512;
        int r = idx >> 5, k4 = idx & 31;
        int gm = m0 + r;
        __half2 p0 = __floats2half2_rn(0.f, 0.f), p1 = p0;
        if (gm < NN) {
            if (Ahp) {
                const __half2* ap = (const __half2*)&Ahp[(long long)gm * 128 + k4 * 4];
                p0 = ap[0];
                p1 = ap[1];
            } else {
                float4 v = *(const float4*)&Af[(long long)gm * 128 + k4 * 4];
                p0 = __floats2half2_rn(v.x, v.y);
                p1 = __floats2half2_rn(v.z, v.w);
            }
        }
        __half2* dst = (__half2*)&As[r * LDH + k4 * 4];
        dst[0] = p0;
        dst[1] = p1;
    }
#pragma unroll
    for (int l = 0; l < 8; l++) {
        int idx = tid + l * 512;
        int r = idx >> 5, c4 = idx & 31;
        float4 v = *(const float4*)&W[r * 128 + c4 * 4];
        __half2* dst = (__half2*)&Ws[r * LDH + c4 * 4];
        dst[0] = __floats2half2_rn(v.x, v.y);
        dst[1] = __floats2half2_rn(v.z, v.w);
    }
    __syncthreads();

    int warp = tid >> 5;
    int mi = warp & 3;    // rows mi*32
    int ni = warp >> 2;   // cols ni*32

    wmma::fragment<wmma::accumulator, 16, 16, 16, float> acc[2][2];
#pragma unroll
    for (int di = 0; di < 2; di++)
#pragma unroll
        for (int dj = 0; dj < 2; dj++) wmma::fill_fragment(acc[di][dj], 0.f);
#pragma unroll
    for (int k = 0; k < 128; k += 16) {
        wmma::fragment<wmma::matrix_a, 16, 16, 16, __half, wmma::row_major> af[2];
        wmma::fragment<wmma::matrix_b, 16, 16, 16, __half, wmma::row_major> bf[2];
#pragma unroll
        for (int di = 0; di < 2; di++)
            wmma::load_matrix_sync(af[di], As + (mi * 32 + di * 16) * LDH + k, LDH);
#pragma unroll
        for (int dj = 0; dj < 2; dj++)
            wmma::load_matrix_sync(bf[dj], Ws + k * LDH + ni * 32 + dj * 16, LDH);
#pragma unroll
        for (int di = 0; di < 2; di++)
#pragma unroll
            for (int dj = 0; dj < 2; dj++)
                wmma::mma_sync(acc[di][dj], af[di], bf[dj], acc[di][dj]);
    }

#pragma unroll
    for (int di = 0; di < 2; di++)
#pragma unroll
        for (int dj = 0; dj < 2; dj++)
            wmma::store_matrix_sync(Est + (mi * 32 + di * 16) * 128 + ni * 32 + dj * 16,
                                    acc[di][dj], 128, wmma::mem_row_major);
    __syncthreads();
#pragma unroll
    for (int l = 0; l < 8; l++) {
        int idx = tid + l * 512;
        int r = idx >> 5, c4 = idx & 31;
        int gr = m0 + r;
        if (gr < NN) {
            float4 vv = *(const float4*)&Est[r * 128 + c4 * 4];
            __half2* op = (__half2*)&O[(long long)gr * 128 + c4 * 4];
            op[0] = __floats2half2_rn(vv.x, vv.y);
            op[1] = __floats2half2_rn(vv.z, vv.w);
        }
    }
}

// ---------------- GCN aggregation, batched over blockIdx.y ----------------
__global__ void gather_conv_k(const __half* __restrict__ hbase,
                              const float* __restrict__ biasbase,
                              __half* __restrict__ outbase) {
    int b = blockIdx.y;
    const __half* h = hbase + (long long)b * NNL * 128;
    __half* out = outbase + (long long)b * NNL * 128;
    const float* bias = biasbase + b * 128;
    const float2* ecc = g_ecc + (long long)b * EE;
    const int* lcnt = g_lcnt + b * NN;
    const float* dinv = g_dinv + b * NN;

    int t = blockIdx.x * blockDim.x + threadIdx.x;
    int v = t >> 5, lane = t & 31;
    if (v >= NN) return;
    int st = g_startC[v];
    int cnt = lcnt[v];
    float4 acc = make_float4(0.f, 0.f, 0.f, 0.f);
    for (int j0 = 0; j0 < cnt; j0 += 32) {
        int i = j0 + lane;
        float2 pr = make_float2(0.f, 0.f);
        if (i < cnt) pr = ecc[st + i];
        int lim = min(32, cnt - j0);
        for (int j = 0; j < lim; j++) {
            float cj = __shfl_sync(0xffffffffu, pr.y, j);
            int uj = __float_as_int(__shfl_sync(0xffffffffu, pr.x, j));
            const __half2* hp = (const __half2*)&h[(long long)uj * 128 + lane * 4];
            float2 lo = __half22float2(hp[0]);
            float2 hi = __half22float2(hp[1]);
            acc.x += cj * lo.x; acc.y += cj * lo.y;
            acc.z += cj * hi.x; acc.w += cj * hi.y;
        }
    }
    float dv = dinv[v];
    const __half2* sp = (const __half2*)&h[(long long)v * 128 + lane * 4];
    float2 slo = __half22float2(sp[0]);
    float2 shi = __half22float2(sp[1]);
    float4 bv = *(const float4*)&bias[lane * 4];
    float ox = fmaxf(bv.x + dv * (acc.x + dv * slo.x), 0.f);
    float oy = fmaxf(bv.y + dv * (acc.y + dv * slo.y), 0.f);
    float oz = fmaxf(bv.z + dv * (acc.z + dv * shi.x), 0.f);
    float ow = fmaxf(bv.w + dv * (acc.w + dv * shi.y), 0.f);
    __half2* op = (__half2*)&out[(long long)v * 128 + lane * 4];
    op[0] = __floats2half2_rn(ox, oy);
    op[1] = __floats2half2_rn(oz, ow);
}

// ---------------- pooling, batched over blockIdx.y ----------------
__global__ void hist_batch_k(const int* __restrict__ batch) {
    int i = blockIdx.x * blockDim.x + threadIdx.x;
    if (i < NN) atomicAdd(&g_cntg[batch[i]], 1);
}

__global__ void pool_k(const __half* __restrict__ zbase, const int* __restrict__ batch) {
    int b = blockIdx.y;
    const __half* z = zbase + (long long)b * NNL * 128;
    int boff = b * 256;
    int f = threadIdx.x;  // 128 threads = one feature each
    int n0 = blockIdx.x * 256;
    if (n0 >= NN) return;
    int nend = min(n0 + 256, NN);
    int cur = batch[n0];
    float ls = 0.f, lm = 0.f;
    for (int n = n0; n < nend; n++) {
        int g = batch[n];
        if (g != cur) {
            atomicAdd(&g_feats[cur * F6 + boff + f], ls);
            atomicMax((int*)&g_feats[cur * F6 + boff + 128 + f], __float_as_int(lm));
            ls = 0.f; lm = 0.f; cur = g;
        }
        float v = __half2float(z[(long long)n * 128 + f]);  // already relu'd (>= 0)
        ls += v;
        lm = fmaxf(lm, v);
    }
    atomicAdd(&g_feats[cur * F6 + boff + f], ls);
    atomicMax((int*)&g_feats[cur * F6 + boff + 128 + f], __float_as_int(lm));
}

// ---------------- tiny MLP head (mean finalize folded into mlp1) ----------------
__global__ void mlp1_k(const float* __restrict__ w, const float* __restrict__ bias) {
    __shared__ float sh[F6];
    int g = blockIdx.x, j = threadIdx.x;  // 256 threads
    float inv = 1.0f / (float)max(g_cntg[g], 1);
    for (int i = j; i < F6; i += 256) {
        float v = g_feats[g * F6 + i];
        if ((i & 255) < 128) v *= inv;  // mean slots: divide by node count
        sh[i] = v;
    }
    __syncthreads();
    float acc = bias[j];
#pragma unroll 8
    for (int i = 0; i < F6; i++) acc += sh[i] * w[i * 256 + j];
    g_mlp1[g * 256 + j] = fmaxf(acc, 0.f);
}

__global__ void mlp2_k(const float* __restrict__ w, const float* __restrict__ bias) {
    __shared__ float sh[256];
    int g = blockIdx.x, j = threadIdx.x;  // 128 threads
    for (int i = j; i < 256; i += 128) sh[i] = g_mlp1[g * 256 + i];
    __syncthreads();
    float acc = bias[j];
#pragma unroll 8
    for (int i = 0; i < 256; i++) acc += sh[i] * w[i * 128 + j];
    g_mlp2[g * 128 + j] = fmaxf(acc, 0.f);
}

__global__ void mlp3_k(const float* __restrict__ w, const float* __restrict__ bias,
                       float* __restrict__ out) {
    int g = blockIdx.x, lane = threadIdx.x;  // 32 threads
    __shared__ float sh[128];
    for (int i = lane; i < 128; i += 32) sh[i] = g_mlp2[g * 128 + i];
    __syncwarp();
    float acc[NCLS];
#pragma unroll
    for (int c = 0; c < NCLS; c++) acc[c] = 0.f;
    for (int i = lane; i < 128; i += 32) {
        float v = sh[i];
#pragma unroll
        for (int c = 0; c < NCLS; c++) acc[c] += v * w[i * NCLS + c];
    }
#pragma unroll
    for (int c = 0; c < NCLS; c++)
#pragma unroll
        for (int o = 16; o > 0; o >>= 1) acc[c] += __shfl_xor_sync(0xffffffffu, acc[c], o);
    if (lane == 0) {
        float vals[NCLS], m = -1e30f;
        for (int c = 0; c < NCLS; c++) { vals[c] = acc[c] + bias[c]; m = fmaxf(m, vals[c]); }
        float s = 0.f;
        for (int c = 0; c < NCLS; c++) s += expf(vals[c] - m);
        float lse = logf(s);
        for (int c = 0; c < NCLS; c++) out[g * NCLS + c] = vals[c] - m - lse;
    }
}

// ---------------- host launch ----------------
extern "C" void kernel_launch(void* const* d_in, const int* in_sizes, int n_in,
                              void* d_out, int out_size) {
    const float* x = (const float*)d_in[0];
    const int* ei = (const int*)d_in[1];
    // d_in[2] = edge_attr: unused by the reference
    const int* batch = (const int*)d_in[3];
    int pi = (n_in >= 16) ? 5 : 4;
    const float* att  = (const float*)d_in[pi + 0];
    const float* W1   = (const float*)d_in[pi + 1];
    const float* b1   = (const float*)d_in[pi + 2];
    const float* W2   = (const float*)d_in[pi + 3];
    const float* b2   = (const float*)d_in[pi + 4];
    const float* fc1w = (const float*)d_in[pi + 5];
    const float* fc1b = (const float*)d_in[pi + 6];
    const float* fc2w = (const float*)d_in[pi + 7];
    const float* fc2b = (const float*)d_in[pi + 8];
    const float* fc3w = (const float*)d_in[pi + 9];
    const float* fc3b = (const float*)d_in[pi + 10];
    float* out = (float*)d_out;

    float* feats;
    __half *h16A, *h16B, *h16C;
    int *cntR, *cntC, *startR, *startC, *curR, *curC;
    int *inclR, *inclC, *bsumR, *bsumC, *cntg;
    cudaGetSymbolAddress((void**)&h16A, g_h16A);
    cudaGetSymbolAddress((void**)&h16B, g_h16B);
    cudaGetSymbolAddress((void**)&h16C, g_h16C);
    cudaGetSymbolAddress((void**)&feats, g_feats);
    cudaGetSymbolAddress((void**)&cntR, g_cntR);
    cudaGetSymbolAddress((void**)&cntC, g_cntC);
    cudaGetSymbolAddress((void**)&startR, g_startR);
    cudaGetSymbolAddress((void**)&startC, g_startC);
    cudaGetSymbolAddress((void**)&curR, g_curR);
    cudaGetSymbolAddress((void**)&curC, g_curC);
    cudaGetSymbolAddress((void**)&inclR, g_inclR);
    cudaGetSymbolAddress((void**)&inclC, g_inclC);
    cudaGetSymbolAddress((void**)&bsumR, g_bsumR);
    cudaGetSymbolAddress((void**)&bsumC, g_bsumC);
    cudaGetSymbolAddress((void**)&cntg, g_cntg);

    cudaFuncSetAttribute(gemm_h16_k, cudaFuncAttributeMaxDynamicSharedMemorySize,
                         GEMM_SMEM_BYTES);

    // side streams + events for capture-compatible fork/join
    static cudaStream_t sA = 0, sB = 0;
    static cudaEvent_t evRoot = 0, evA = 0, evB = 0;
    if (!sA) {
        cudaStreamCreateWithFlags(&sA, cudaStreamNonBlocking);
        cudaStreamCreateWithFlags(&sB, cudaStreamNonBlocking);
        cudaEventCreateWithFlags(&evRoot, cudaEventDisableTiming);
        cudaEventCreateWithFlags(&evA, cudaEventDisableTiming);
        cudaEventCreateWithFlags(&evB, cudaEventDisableTiming);
    }

    const int* row = ei;
    const int* col = ei + EE;

    cudaMemsetAsync(cntR, 0, NN * sizeof(int));
    cudaMemsetAsync(cntC, 0, NN * sizeof(int));
    cudaMemsetAsync(cntg, 0, GG * sizeof(int));
    cudaMemsetAsync(feats, 0, GG * F6 * sizeof(float));
    cudaEventRecord(evRoot, 0);

    // branch A: batched conv1 GEMM — depends only on x, W1
    cudaStreamWaitEvent(sA, evRoot, 0);
    gemm_h16_k<<<dim3(cdiv(NN, 128), 3), 512, GEMM_SMEM_BYTES, sA>>>(
        x, (const __half*)0, 0ll, W1, h16A, NNL * 128);
    cudaEventRecord(evA, sA);

    // branch B: attention scores + per-graph counts
    cudaStreamWaitEvent(sB, evRoot, 0);
    s12_k<<<cdiv(NN * 32, 256), 256, 0, sB>>>(x, att);
    hist_batch_k<<<cdiv(NN, 256), 256, 0, sB>>>(batch);
    cudaEventRecord(evB, sB);

    // main branch: CSR/CSC build
    hist_e<<<cdiv(EE, 256), 256>>>(row, col);
    scan_local<<<NB, 1024>>>(cntR, inclR, bsumR, cntC, inclC, bsumC);
    scan_mid_k<<<1, 128>>>();
    scan_final<<<NB, 1024>>>(cntR, inclR, bsumR, startR, curR,
                             cntC, inclC, bsumC, startC, curC);
    scatter_e<<<cdiv(EE, 256), 256>>>(row, col);

    // join B: sparsemax needs s1/s2 + CSR
    cudaStreamWaitEvent(0, evB, 0);
    sparsemax_all_k<<<cdiv(NN, 8), 256>>>();
    dinv_all_k<<<cdiv(NN * 32, 256), 256>>>();
    ecoef_compact_k<<<cdiv(NN * 32, 256), 256>>>();

    // join A: gathers need the conv1 GEMM output
    cudaStreamWaitEvent(0, evA, 0);
    gather_conv_k<<<dim3(cdiv(NN * 32, 256), 3), 256>>>(h16A, b1, h16B);
    gemm_h16_k<<<dim3(cdiv(NN, 128), 3), 512, GEMM_SMEM_BYTES>>>(
        (const float*)0, h16B, NNL * 128, W2, h16C, NNL * 128);
    gather_conv_k<<<dim3(cdiv(NN * 32, 256), 3), 256>>>(h16C, b2, h16A);
    pool_k<<<dim3(cdiv(NN, 256), 3), 128>>>(h16A, batch);

    mlp1_k<<<GG, 256>>>(fc1w, fc1b);
    mlp2_k<<<GG, 128>>>(fc2w, fc2b);
    mlp3_k<<<GG, 32>>>(fc3w, fc3b, out);

    (void)in_sizes;
    (void)out_size;
}